// round 4
// baseline (speedup 1.0000x reference)
#include <cuda_runtime.h>
#include <math.h>
#include <stdint.h>

#define D_MODEL 1024
#define NH 16
#define DH 64
#define BATCH 4
#define SEQ 1024
#define MROWS (BATCH*SEQ)        // 4096
#define QK_COUNT 4194304.0f
#define EPS 1e-6f

// ---------------- scratch ---------------------------------------------------
__device__ float g_qkv[MROWS * 3 * D_MODEL];
__device__ float g_z[MROWS * D_MODEL];
__device__ float g_sumsq[2];
__device__ float g_inv[2];

// ---------------- tiny kernels ----------------------------------------------
__global__ void zero2_kernel(float* p) { if (threadIdx.x < 2) p[threadIdx.x] = 0.0f; }

__global__ void finalize_kernel(const float* __restrict__ ss, float* __restrict__ inv) {
    if (threadIdx.x < 2) {
        float rms = sqrtf(ss[threadIdx.x] / QK_COUNT);
        inv[threadIdx.x] = 1.0f / (rms + EPS);
    }
}

// ---------------- mma.sync tf32 helpers --------------------------------------
__device__ __forceinline__ uint32_t f2tf32(float x) {
    uint32_t u; asm("cvt.rna.tf32.f32 %0, %1;" : "=r"(u) : "f"(x)); return u;
}
// split x into hi (tf32) and lo (tf32 of remainder)
__device__ __forceinline__ void tf32_split(float x, uint32_t& hi, uint32_t& lo) {
    hi = f2tf32(x);
    lo = f2tf32(x - __uint_as_float(hi));
}

__device__ __forceinline__ void mma_tf32(float* d, const uint32_t* a, const uint32_t* b) {
    asm volatile(
        "mma.sync.aligned.m16n8k8.row.col.f32.tf32.tf32.f32 "
        "{%0,%1,%2,%3}, {%4,%5,%6,%7}, {%8,%9}, {%0,%1,%2,%3};"
        : "+f"(d[0]), "+f"(d[1]), "+f"(d[2]), "+f"(d[3])
        : "r"(a[0]), "r"(a[1]), "r"(a[2]), "r"(a[3]), "r"(b[0]), "r"(b[1]));
}

// ---------------- 3xTF32 tensor-core GEMM ------------------------------------
// C[M,N] = A[M,K] @ B[K,N] with error-compensated tf32 (hi*hi + hi*lo + lo*hi).
// Block 128x128, BK=32, 256 threads (8 warps 2x4), warp tile 64x32 via 4x4
// m16n8k8 fragments. Double-buffered smem; per stage: A_hi, A_lo, B_hi, B_lo
// each [128][36] u32 (stride 36 -> conflict-free quad fragment loads).
#define AS_STR 36
#define ARR_F  (128 * AS_STR)               // one array
#define STAGE_F (4 * ARR_F)                 // floats per stage
#define GEMM_SMEM (2 * STAGE_F * 4)         // 147456 bytes

__global__ __launch_bounds__(256, 1)
void gemm_mma_kernel(const float* __restrict__ A, const float* __restrict__ B,
                     float* __restrict__ C, int N, int K,
                     float* sumsq, int do_sumsq)
{
    extern __shared__ float sm[];
    __shared__ float red[256];

    const int tid = threadIdx.x;
    const int wid = tid >> 5;
    const int lid = tid & 31;
    const int warp_m = wid >> 2;        // 0..1
    const int warp_n = wid & 3;         // 0..3
    const int gr = lid >> 2;            // 0..7
    const int tc = lid & 3;             // 0..3
    const int bcol = blockIdx.x;
    const int brow = blockIdx.y;

    const float* Ag = A + (size_t)brow * 128 * K;
    const float* Bg = B + (size_t)bcol * 128;
    const int KT = K / 32;

    float acc[4][4][4];
#pragma unroll
    for (int i = 0; i < 4; i++)
#pragma unroll
        for (int j = 0; j < 4; j++)
#pragma unroll
            for (int c = 0; c < 4; c++) acc[i][j][c] = 0.0f;

    const int a_r  = tid >> 3;
    const int a_kc = (tid & 7) * 4;
    const int b_k  = tid >> 5;
    const int b_n4 = (tid & 31) * 4;

    float4 ra[4], rb[4];

    auto ldg_tile = [&](int k0) {
#pragma unroll
        for (int l = 0; l < 4; l++) {
            int r = a_r + l * 32;
            ra[l] = *(const float4*)(Ag + (size_t)r * K + k0 + a_kc);
        }
#pragma unroll
        for (int l = 0; l < 4; l++) {
            int k = b_k + l * 8;
            rb[l] = *(const float4*)(Bg + (size_t)(k0 + k) * N + b_n4);
        }
    };

    auto sts_tile = [&](int stage) {
        uint32_t* Ah = (uint32_t*)(sm + stage * STAGE_F);
        uint32_t* Al = Ah + ARR_F;
        uint32_t* Bh = Al + ARR_F;
        uint32_t* Bl = Bh + ARR_F;
#pragma unroll
        for (int l = 0; l < 4; l++) {
            int r = a_r + l * 32;
            uint32_t h0,l0,h1,l1,h2,l2,h3,l3;
            tf32_split(ra[l].x, h0, l0); tf32_split(ra[l].y, h1, l1);
            tf32_split(ra[l].z, h2, l2); tf32_split(ra[l].w, h3, l3);
            uint32_t* ph = Ah + r * AS_STR + a_kc;
            uint32_t* pl = Al + r * AS_STR + a_kc;
            *(uint2*)(ph)     = make_uint2(h0, h1);
            *(uint2*)(ph + 2) = make_uint2(h2, h3);
            *(uint2*)(pl)     = make_uint2(l0, l1);
            *(uint2*)(pl + 2) = make_uint2(l2, l3);
        }
#pragma unroll
        for (int l = 0; l < 4; l++) {
            int k = b_k + l * 8;
            uint32_t h0,l0,h1,l1,h2,l2,h3,l3;
            tf32_split(rb[l].x, h0, l0); tf32_split(rb[l].y, h1, l1);
            tf32_split(rb[l].z, h2, l2); tf32_split(rb[l].w, h3, l3);
            Bh[(b_n4 + 0) * AS_STR + k] = h0;  Bl[(b_n4 + 0) * AS_STR + k] = l0;
            Bh[(b_n4 + 1) * AS_STR + k] = h1;  Bl[(b_n4 + 1) * AS_STR + k] = l1;
            Bh[(b_n4 + 2) * AS_STR + k] = h2;  Bl[(b_n4 + 2) * AS_STR + k] = l2;
            Bh[(b_n4 + 3) * AS_STR + k] = h3;  Bl[(b_n4 + 3) * AS_STR + k] = l3;
        }
    };

    ldg_tile(0);
    sts_tile(0);

    for (int t = 0; t < KT; t++) {
        const int s = t & 1;
        if (t + 1 < KT) ldg_tile((t + 1) * 32);
        __syncthreads();
        if (t + 1 < KT) sts_tile(s ^ 1);

        const uint32_t* Ah = (const uint32_t*)(sm + s * STAGE_F);
        const uint32_t* Al = Ah + ARR_F;
        const uint32_t* Bh = Al + ARR_F;
        const uint32_t* Bl = Bh + ARR_F;

#pragma unroll
        for (int ks = 0; ks < 4; ks++) {
            const int k = ks * 8;
            uint32_t afh[4][4], afl[4][4], bfh[4][2], bfl[4][2];
#pragma unroll
            for (int i = 0; i < 4; i++) {
                const int m0 = (warp_m * 64 + i * 16 + gr) * AS_STR + k + tc;
                afh[i][0] = Ah[m0];             afh[i][1] = Ah[m0 + 8 * AS_STR];
                afh[i][2] = Ah[m0 + 4];         afh[i][3] = Ah[m0 + 8 * AS_STR + 4];
                afl[i][0] = Al[m0];             afl[i][1] = Al[m0 + 8 * AS_STR];
                afl[i][2] = Al[m0 + 4];         afl[i][3] = Al[m0 + 8 * AS_STR + 4];
            }
#pragma unroll
            for (int j = 0; j < 4; j++) {
                const int n0 = (warp_n * 32 + j * 8 + gr) * AS_STR + k + tc;
                bfh[j][0] = Bh[n0];  bfh[j][1] = Bh[n0 + 4];
                bfl[j][0] = Bl[n0];  bfl[j][1] = Bl[n0 + 4];
            }
#pragma unroll
            for (int i = 0; i < 4; i++)
#pragma unroll
                for (int j = 0; j < 4; j++) {
                    mma_tf32(acc[i][j], afl[i], bfh[j]);   // lo*hi
                    mma_tf32(acc[i][j], afh[i], bfl[j]);   // hi*lo
                    mma_tf32(acc[i][j], afh[i], bfh[j]);   // hi*hi
                }
        }
        __syncthreads();
    }

    // ---- epilogue: write C, fused sum-of-squares over q/k column regions ----
    const int colbase = bcol * 128;
    float ss = 0.0f;
#pragma unroll
    for (int i = 0; i < 4; i++) {
        const int row0 = brow * 128 + warp_m * 64 + i * 16 + gr;
#pragma unroll
        for (int j = 0; j < 4; j++) {
            const int col = colbase + warp_n * 32 + j * 8 + tc * 2;
            float2 d0 = make_float2(acc[i][j][0], acc[i][j][1]);
            float2 d1 = make_float2(acc[i][j][2], acc[i][j][3]);
            *(float2*)(C + (size_t)row0 * N + col)       = d0;
            *(float2*)(C + (size_t)(row0 + 8) * N + col) = d1;
            if (do_sumsq && colbase < 2048)
                ss += d0.x*d0.x + d0.y*d0.y + d1.x*d1.x + d1.y*d1.y;
        }
    }

    if (do_sumsq && colbase < 2048) {
        red[tid] = ss;
        __syncthreads();
        for (int s2 = 128; s2 > 0; s2 >>= 1) {
            if (tid < s2) red[tid] += red[tid + s2];
            __syncthreads();
        }
        if (tid == 0) atomicAdd(&sumsq[colbase < 1024 ? 0 : 1], red[0]);
    }
}

// ---------------- Flash attention (unchanged, passing @491us) ----------------
__global__ __launch_bounds__(256)
void flash_kernel(const float* __restrict__ qkv, const float* __restrict__ inv,
                  const float* __restrict__ scale_q, const float* __restrict__ scale_k,
                  float* __restrict__ z)
{
    extern __shared__ float sm[];
    float* Qst = sm;
    float* Kst = Qst + 64 * 132;
    float* Vs  = Kst + 64 * 68;
    float* Pst = Vs  + 64 * 68;

    const int tid = threadIdx.x;
    const int qt  = blockIdx.x;
    const int h   = blockIdx.y;
    const int b   = blockIdx.z;
    const int trow = (tid >> 4) * 8;
    const int tcol = (tid & 15) * 4;

    const float invq = inv[0];
    const float invk = inv[1];

    {
        const int base = b * SEQ + qt * 128;
#pragma unroll
        for (int l = 0; l < 8; l++) {
            int idx = tid + l * 256;
            int r   = idx >> 4;
            int d   = (idx & 15) * 4;
            float4 v = *(const float4*)(qkv + (size_t)(base + r) * 3072 + h * DH + d);
            Qst[(d + 0) * 132 + r] = v.x * invq * scale_q[d + 0];
            Qst[(d + 1) * 132 + r] = v.y * invq * scale_q[d + 1];
            Qst[(d + 2) * 132 + r] = v.z * invq * scale_q[d + 2];
            Qst[(d + 3) * 132 + r] = v.w * invq * scale_q[d + 3];
        }
    }

    float o[8][4];
    float mrow[8], lrow[8];
#pragma unroll
    for (int i = 0; i < 8; i++) {
        mrow[i] = -INFINITY; lrow[i] = 0.0f;
#pragma unroll
        for (int j = 0; j < 4; j++) o[i][j] = 0.0f;
    }

    for (int t = 0; t < 16; t++) {
        __syncthreads();
#pragma unroll
        for (int u = 0; u < 4; u++) {
            int idx = tid + u * 256;
            int c   = idx >> 4;
            int d   = (idx & 15) * 4;
            int srow = b * SEQ + t * 64 + c;
            float4 kv = *(const float4*)(qkv + (size_t)srow * 3072 + 1024 + h * DH + d);
            Kst[(d + 0) * 68 + c] = kv.x * invk * scale_k[d + 0];
            Kst[(d + 1) * 68 + c] = kv.y * invk * scale_k[d + 1];
            Kst[(d + 2) * 68 + c] = kv.z * invk * scale_k[d + 2];
            Kst[(d + 3) * 68 + c] = kv.w * invk * scale_k[d + 3];
            float4 vv = *(const float4*)(qkv + (size_t)srow * 3072 + 2048 + h * DH + d);
            *(float4*)&Vs[c * 68 + d] = vv;
        }
        __syncthreads();

        float sreg[8][4];
#pragma unroll
        for (int i = 0; i < 8; i++)
#pragma unroll
            for (int j = 0; j < 4; j++) sreg[i][j] = 0.0f;

#pragma unroll 8
        for (int d = 0; d < 64; d++) {
            float4 a0 = *(const float4*)&Qst[d * 132 + trow];
            float4 a1 = *(const float4*)&Qst[d * 132 + trow + 4];
            float4 bb = *(const float4*)&Kst[d * 68 + tcol];
            float av[8] = {a0.x, a0.y, a0.z, a0.w, a1.x, a1.y, a1.z, a1.w};
            float bv[4] = {bb.x, bb.y, bb.z, bb.w};
#pragma unroll
            for (int i = 0; i < 8; i++)
#pragma unroll
                for (int j = 0; j < 4; j++)
                    sreg[i][j] = fmaf(av[i], bv[j], sreg[i][j]);
        }

#pragma unroll
        for (int i = 0; i < 8; i++) {
            float tmax = fmaxf(fmaxf(sreg[i][0], sreg[i][1]), fmaxf(sreg[i][2], sreg[i][3]));
#pragma unroll
            for (int off = 8; off >= 1; off >>= 1)
                tmax = fmaxf(tmax, __shfl_xor_sync(0xffffffffu, tmax, off));
            float mnew = fmaxf(mrow[i], tmax);
            float corr = __expf(mrow[i] - mnew);
            float psum = 0.0f;
#pragma unroll
            for (int j = 0; j < 4; j++) {
                float p = __expf(sreg[i][j] - mnew);
                psum += p;
                Pst[(tcol + j) * 132 + (trow + i)] = p;
            }
#pragma unroll
            for (int off = 8; off >= 1; off >>= 1)
                psum += __shfl_xor_sync(0xffffffffu, psum, off);
            lrow[i] = lrow[i] * corr + psum;
            mrow[i] = mnew;
#pragma unroll
            for (int j = 0; j < 4; j++) o[i][j] *= corr;
        }
        __syncthreads();

#pragma unroll 8
        for (int j = 0; j < 64; j++) {
            float4 p0 = *(const float4*)&Pst[j * 132 + trow];
            float4 p1 = *(const float4*)&Pst[j * 132 + trow + 4];
            float4 vv = *(const float4*)&Vs[j * 68 + tcol];
            float pv[8] = {p0.x, p0.y, p0.z, p0.w, p1.x, p1.y, p1.z, p1.w};
            float vvv[4] = {vv.x, vv.y, vv.z, vv.w};
#pragma unroll
            for (int i = 0; i < 8; i++)
#pragma unroll
                for (int c = 0; c < 4; c++)
                    o[i][c] = fmaf(pv[i], vvv[c], o[i][c]);
        }
    }

#pragma unroll
    for (int i = 0; i < 8; i++) {
        float rl = 1.0f / lrow[i];
        float4 out = {o[i][0] * rl, o[i][1] * rl, o[i][2] * rl, o[i][3] * rl};
        int row = b * SEQ + qt * 128 + trow + i;
        *(float4*)(z + (size_t)row * D_MODEL + h * DH + tcol) = out;
    }
}

// ---------------- launcher ----------------------------------------------------
extern "C" void kernel_launch(void* const* d_in, const int* in_sizes, int n_in,
                              void* d_out, int out_size)
{
    const float* x    = (const float*)d_in[0];
    const float* Wqkv = (const float*)d_in[1];
    const float* Wo   = (const float*)d_in[2];
    const float* sq   = (const float*)d_in[3];
    const float* sk   = (const float*)d_in[4];
    float* out = (float*)d_out;

    float *qkv, *z, *ss, *inv;
    cudaGetSymbolAddress((void**)&qkv, g_qkv);
    cudaGetSymbolAddress((void**)&z,   g_z);
    cudaGetSymbolAddress((void**)&ss,  g_sumsq);
    cudaGetSymbolAddress((void**)&inv, g_inv);

    static bool attr_done = false;
    if (!attr_done) {
        cudaFuncSetAttribute(gemm_mma_kernel, cudaFuncAttributeMaxDynamicSharedMemorySize, GEMM_SMEM);
        cudaFuncSetAttribute(flash_kernel, cudaFuncAttributeMaxDynamicSharedMemorySize, 102400);
        attr_done = true;
    }

    zero2_kernel<<<1, 32>>>(ss);

    gemm_mma_kernel<<<dim3(3 * D_MODEL / 128, MROWS / 128), 256, GEMM_SMEM>>>(
        x, Wqkv, qkv, 3 * D_MODEL, D_MODEL, ss, 1);

    finalize_kernel<<<1, 32>>>(ss, inv);

    flash_kernel<<<dim3(SEQ / 128, NH, BATCH), 256, 102400>>>(qkv, inv, sq, sk, z);

    gemm_mma_kernel<<<dim3(D_MODEL / 128, MROWS / 128), 256, GEMM_SMEM>>>(
        z, Wo, out, D_MODEL, D_MODEL, nullptr, 0);
}

// round 5
// speedup vs baseline: 1.1435x; 1.1435x over previous
#include <cuda_runtime.h>
#include <cuda_fp16.h>
#include <math.h>
#include <stdint.h>

#define D_MODEL 1024
#define NH 16
#define DH 64
#define BATCH 4
#define SEQ 1024
#define MROWS (BATCH*SEQ)        // 4096
#define QK_COUNT 4194304.0f
#define EPS 1e-6f

// ---------------- scratch ---------------------------------------------------
__device__ float g_qkv[MROWS * 3 * D_MODEL];
__device__ float g_z[MROWS * D_MODEL];
__device__ float g_sumsq[2];
__device__ float g_inv[2];

// ---------------- tiny kernels ----------------------------------------------
__global__ void zero2_kernel(float* p) { if (threadIdx.x < 2) p[threadIdx.x] = 0.0f; }

__global__ void finalize_kernel(const float* __restrict__ ss, float* __restrict__ inv) {
    if (threadIdx.x < 2) {
        float rms = sqrtf(ss[threadIdx.x] / QK_COUNT);
        inv[threadIdx.x] = 1.0f / (rms + EPS);
    }
}

// ---------------- fp16-split mma helpers --------------------------------------
__device__ __forceinline__ void f16_split(float x, uint16_t& h, uint16_t& l) {
    __half hh = __float2half_rn(x);
    __half ll = __float2half_rn(x - __half2float(hh));
    h = __half_as_ushort(hh);
    l = __half_as_ushort(ll);
}
__device__ __forceinline__ uint32_t pack2(uint16_t a, uint16_t b) {
    return (uint32_t)a | ((uint32_t)b << 16);
}

__device__ __forceinline__ void mma_f16(float* d, const uint32_t* a, const uint32_t* b) {
    asm volatile(
        "mma.sync.aligned.m16n8k16.row.col.f32.f16.f16.f32 "
        "{%0,%1,%2,%3}, {%4,%5,%6,%7}, {%8,%9}, {%0,%1,%2,%3};"
        : "+f"(d[0]), "+f"(d[1]), "+f"(d[2]), "+f"(d[3])
        : "r"(a[0]), "r"(a[1]), "r"(a[2]), "r"(a[3]), "r"(b[0]), "r"(b[1]));
}

// ---------------- fp16x2-split tensor-core GEMM -------------------------------
// C[M,N] = A[M,K] @ B[K,N], error-compensated fp16 (hi*hi + hi*lo + lo*hi;
// lo*lo ~ 2^-22 dropped). Block 128x128, BK=32, 256 threads (8 warps 2x4),
// warp tile 64x32 via 4x4 m16n8k16 fragments, 2 k-steps per BK tile.
// Smem per stage: A_hi, A_lo, B_hi, B_lo each [128][40] halves (stride 40
// -> conflict-free fragment loads). 40960 B/stage, double buffered = 81920 B.
#define HS_STR 40
#define ARR_H  (128 * HS_STR)               // halves per array
#define STAGE_H (4 * ARR_H)                 // halves per stage
#define GEMM_SMEM (2 * STAGE_H * 2)         // bytes = 81920

__global__ __launch_bounds__(256, 1)
void gemm_mma_kernel(const float* __restrict__ A, const float* __restrict__ B,
                     float* __restrict__ C, int N, int K,
                     float* sumsq, int do_sumsq)
{
    extern __shared__ uint16_t smh[];
    __shared__ float red[256];

    const int tid = threadIdx.x;
    const int wid = tid >> 5;
    const int lid = tid & 31;
    const int warp_m = wid >> 2;        // 0..1
    const int warp_n = wid & 3;         // 0..3
    const int gr = lid >> 2;            // 0..7
    const int tc = lid & 3;             // 0..3
    const int bcol = blockIdx.x;
    const int brow = blockIdx.y;

    const float* Ag = A + (size_t)brow * 128 * K;
    const float* Bg = B + (size_t)bcol * 128;
    const int KT = K / 32;

    float acc[4][4][4];
#pragma unroll
    for (int i = 0; i < 4; i++)
#pragma unroll
        for (int j = 0; j < 4; j++)
#pragma unroll
            for (int c = 0; c < 4; c++) acc[i][j][c] = 0.0f;

    const int a_r  = tid >> 3;          // 0..31 (+32 per l)
    const int a_kc = (tid & 7) * 4;     // k offset 0..28
    const int b_k  = tid >> 5;          // 0..7 (+8 per l)
    const int b_n4 = (tid & 31) * 4;    // n offset

    float4 ra[4], rb[4];

    auto ldg_tile = [&](int k0) {
#pragma unroll
        for (int l = 0; l < 4; l++) {
            int r = a_r + l * 32;
            ra[l] = *(const float4*)(Ag + (size_t)r * K + k0 + a_kc);
        }
#pragma unroll
        for (int l = 0; l < 4; l++) {
            int k = b_k + l * 8;
            rb[l] = *(const float4*)(Bg + (size_t)(k0 + k) * N + b_n4);
        }
    };

    auto sts_tile = [&](int stage) {
        uint16_t* Ah = smh + stage * STAGE_H;
        uint16_t* Al = Ah + ARR_H;
        uint16_t* Bh = Al + ARR_H;
        uint16_t* Bl = Bh + ARR_H;
#pragma unroll
        for (int l = 0; l < 4; l++) {
            int r = a_r + l * 32;
            uint16_t h0,l0,h1,l1,h2,l2,h3,l3;
            f16_split(ra[l].x, h0, l0); f16_split(ra[l].y, h1, l1);
            f16_split(ra[l].z, h2, l2); f16_split(ra[l].w, h3, l3);
            int off = r * HS_STR + a_kc;
            *(uint2*)(Ah + off) = make_uint2(pack2(h0, h1), pack2(h2, h3));
            *(uint2*)(Al + off) = make_uint2(pack2(l0, l1), pack2(l2, l3));
        }
#pragma unroll
        for (int l = 0; l < 4; l++) {
            int k = b_k + l * 8;
            uint16_t h0,l0,h1,l1,h2,l2,h3,l3;
            f16_split(rb[l].x, h0, l0); f16_split(rb[l].y, h1, l1);
            f16_split(rb[l].z, h2, l2); f16_split(rb[l].w, h3, l3);
            Bh[(b_n4 + 0) * HS_STR + k] = h0;  Bl[(b_n4 + 0) * HS_STR + k] = l0;
            Bh[(b_n4 + 1) * HS_STR + k] = h1;  Bl[(b_n4 + 1) * HS_STR + k] = l1;
            Bh[(b_n4 + 2) * HS_STR + k] = h2;  Bl[(b_n4 + 2) * HS_STR + k] = l2;
            Bh[(b_n4 + 3) * HS_STR + k] = h3;  Bl[(b_n4 + 3) * HS_STR + k] = l3;
        }
    };

    ldg_tile(0);
    sts_tile(0);

    for (int t = 0; t < KT; t++) {
        const int s = t & 1;
        if (t + 1 < KT) ldg_tile((t + 1) * 32);
        __syncthreads();
        if (t + 1 < KT) sts_tile(s ^ 1);

        const uint16_t* Ah = smh + s * STAGE_H;
        const uint16_t* Al = Ah + ARR_H;
        const uint16_t* Bh = Al + ARR_H;
        const uint16_t* Bl = Bh + ARR_H;

#pragma unroll
        for (int ks = 0; ks < 2; ks++) {
            const int kk = ks * 16;
            uint32_t afh[4][4], afl[4][4], bfh[4][2], bfl[4][2];
#pragma unroll
            for (int i = 0; i < 4; i++) {
                // a0: [gr][kk+2tc], a1: [gr+8][..], a2: [gr][kk+8+2tc], a3: [gr+8][..]
                const int base = (warp_m * 64 + i * 16 + gr) * HS_STR + kk + 2 * tc;
                afh[i][0] = *(const uint32_t*)(Ah + base);
                afh[i][1] = *(const uint32_t*)(Ah + base + 8 * HS_STR);
                afh[i][2] = *(const uint32_t*)(Ah + base + 8);
                afh[i][3] = *(const uint32_t*)(Ah + base + 8 * HS_STR + 8);
                afl[i][0] = *(const uint32_t*)(Al + base);
                afl[i][1] = *(const uint32_t*)(Al + base + 8 * HS_STR);
                afl[i][2] = *(const uint32_t*)(Al + base + 8);
                afl[i][3] = *(const uint32_t*)(Al + base + 8 * HS_STR + 8);
            }
#pragma unroll
            for (int j = 0; j < 4; j++) {
                const int base = (warp_n * 32 + j * 8 + gr) * HS_STR + kk + 2 * tc;
                bfh[j][0] = *(const uint32_t*)(Bh + base);
                bfh[j][1] = *(const uint32_t*)(Bh + base + 8);
                bfl[j][0] = *(const uint32_t*)(Bl + base);
                bfl[j][1] = *(const uint32_t*)(Bl + base + 8);
            }
#pragma unroll
            for (int i = 0; i < 4; i++)
#pragma unroll
                for (int j = 0; j < 4; j++) {
                    mma_f16(acc[i][j], afl[i], bfh[j]);   // lo*hi
                    mma_f16(acc[i][j], afh[i], bfl[j]);   // hi*lo
                    mma_f16(acc[i][j], afh[i], bfh[j]);   // hi*hi
                }
        }
        __syncthreads();
    }

    // ---- epilogue: write C, fused sum-of-squares over q/k column regions ----
    const int colbase = bcol * 128;
    float ss = 0.0f;
#pragma unroll
    for (int i = 0; i < 4; i++) {
        const int row0 = brow * 128 + warp_m * 64 + i * 16 + gr;
#pragma unroll
        for (int j = 0; j < 4; j++) {
            const int col = colbase + warp_n * 32 + j * 8 + tc * 2;
            float2 d0 = make_float2(acc[i][j][0], acc[i][j][1]);
            float2 d1 = make_float2(acc[i][j][2], acc[i][j][3]);
            *(float2*)(C + (size_t)row0 * N + col)       = d0;
            *(float2*)(C + (size_t)(row0 + 8) * N + col) = d1;
            if (do_sumsq && colbase < 2048)
                ss += d0.x*d0.x + d0.y*d0.y + d1.x*d1.x + d1.y*d1.y;
        }
    }

    if (do_sumsq && colbase < 2048) {
        red[tid] = ss;
        __syncthreads();
        for (int s2 = 128; s2 > 0; s2 >>= 1) {
            if (tid < s2) red[tid] += red[tid + s2];
            __syncthreads();
        }
        if (tid == 0) atomicAdd(&sumsq[colbase < 1024 ? 0 : 1], red[0]);
    }
}

// ---------------- Flash attention (unchanged, passing @491us) ----------------
__global__ __launch_bounds__(256)
void flash_kernel(const float* __restrict__ qkv, const float* __restrict__ inv,
                  const float* __restrict__ scale_q, const float* __restrict__ scale_k,
                  float* __restrict__ z)
{
    extern __shared__ float sm[];
    float* Qst = sm;
    float* Kst = Qst + 64 * 132;
    float* Vs  = Kst + 64 * 68;
    float* Pst = Vs  + 64 * 68;

    const int tid = threadIdx.x;
    const int qt  = blockIdx.x;
    const int h   = blockIdx.y;
    const int b   = blockIdx.z;
    const int trow = (tid >> 4) * 8;
    const int tcol = (tid & 15) * 4;

    const float invq = inv[0];
    const float invk = inv[1];

    {
        const int base = b * SEQ + qt * 128;
#pragma unroll
        for (int l = 0; l < 8; l++) {
            int idx = tid + l * 256;
            int r   = idx >> 4;
            int d   = (idx & 15) * 4;
            float4 v = *(const float4*)(qkv + (size_t)(base + r) * 3072 + h * DH + d);
            Qst[(d + 0) * 132 + r] = v.x * invq * scale_q[d + 0];
            Qst[(d + 1) * 132 + r] = v.y * invq * scale_q[d + 1];
            Qst[(d + 2) * 132 + r] = v.z * invq * scale_q[d + 2];
            Qst[(d + 3) * 132 + r] = v.w * invq * scale_q[d + 3];
        }
    }

    float o[8][4];
    float mrow[8], lrow[8];
#pragma unroll
    for (int i = 0; i < 8; i++) {
        mrow[i] = -INFINITY; lrow[i] = 0.0f;
#pragma unroll
        for (int j = 0; j < 4; j++) o[i][j] = 0.0f;
    }

    for (int t = 0; t < 16; t++) {
        __syncthreads();
#pragma unroll
        for (int u = 0; u < 4; u++) {
            int idx = tid + u * 256;
            int c   = idx >> 4;
            int d   = (idx & 15) * 4;
            int srow = b * SEQ + t * 64 + c;
            float4 kv = *(const float4*)(qkv + (size_t)srow * 3072 + 1024 + h * DH + d);
            Kst[(d + 0) * 68 + c] = kv.x * invk * scale_k[d + 0];
            Kst[(d + 1) * 68 + c] = kv.y * invk * scale_k[d + 1];
            Kst[(d + 2) * 68 + c] = kv.z * invk * scale_k[d + 2];
            Kst[(d + 3) * 68 + c] = kv.w * invk * scale_k[d + 3];
            float4 vv = *(const float4*)(qkv + (size_t)srow * 3072 + 2048 + h * DH + d);
            *(float4*)&Vs[c * 68 + d] = vv;
        }
        __syncthreads();

        float sreg[8][4];
#pragma unroll
        for (int i = 0; i < 8; i++)
#pragma unroll
            for (int j = 0; j < 4; j++) sreg[i][j] = 0.0f;

#pragma unroll 8
        for (int d = 0; d < 64; d++) {
            float4 a0 = *(const float4*)&Qst[d * 132 + trow];
            float4 a1 = *(const float4*)&Qst[d * 132 + trow + 4];
            float4 bb = *(const float4*)&Kst[d * 68 + tcol];
            float av[8] = {a0.x, a0.y, a0.z, a0.w, a1.x, a1.y, a1.z, a1.w};
            float bv[4] = {bb.x, bb.y, bb.z, bb.w};
#pragma unroll
            for (int i = 0; i < 8; i++)
#pragma unroll
                for (int j = 0; j < 4; j++)
                    sreg[i][j] = fmaf(av[i], bv[j], sreg[i][j]);
        }

#pragma unroll
        for (int i = 0; i < 8; i++) {
            float tmax = fmaxf(fmaxf(sreg[i][0], sreg[i][1]), fmaxf(sreg[i][2], sreg[i][3]));
#pragma unroll
            for (int off = 8; off >= 1; off >>= 1)
                tmax = fmaxf(tmax, __shfl_xor_sync(0xffffffffu, tmax, off));
            float mnew = fmaxf(mrow[i], tmax);
            float corr = __expf(mrow[i] - mnew);
            float psum = 0.0f;
#pragma unroll
            for (int j = 0; j < 4; j++) {
                float p = __expf(sreg[i][j] - mnew);
                psum += p;
                Pst[(tcol + j) * 132 + (trow + i)] = p;
            }
#pragma unroll
            for (int off = 8; off >= 1; off >>= 1)
                psum += __shfl_xor_sync(0xffffffffu, psum, off);
            lrow[i] = lrow[i] * corr + psum;
            mrow[i] = mnew;
#pragma unroll
            for (int j = 0; j < 4; j++) o[i][j] *= corr;
        }
        __syncthreads();

#pragma unroll 8
        for (int j = 0; j < 64; j++) {
            float4 p0 = *(const float4*)&Pst[j * 132 + trow];
            float4 p1 = *(const float4*)&Pst[j * 132 + trow + 4];
            float4 vv = *(const float4*)&Vs[j * 68 + tcol];
            float pv[8] = {p0.x, p0.y, p0.z, p0.w, p1.x, p1.y, p1.z, p1.w};
            float vvv[4] = {vv.x, vv.y, vv.z, vv.w};
#pragma unroll
            for (int i = 0; i < 8; i++)
#pragma unroll
                for (int c = 0; c < 4; c++)
                    o[i][c] = fmaf(pv[i], vvv[c], o[i][c]);
        }
    }

#pragma unroll
    for (int i = 0; i < 8; i++) {
        float rl = 1.0f / lrow[i];
        float4 out = {o[i][0] * rl, o[i][1] * rl, o[i][2] * rl, o[i][3] * rl};
        int row = b * SEQ + qt * 128 + trow + i;
        *(float4*)(z + (size_t)row * D_MODEL + h * DH + tcol) = out;
    }
}

// ---------------- launcher ----------------------------------------------------
extern "C" void kernel_launch(void* const* d_in, const int* in_sizes, int n_in,
                              void* d_out, int out_size)
{
    const float* x    = (const float*)d_in[0];
    const float* Wqkv = (const float*)d_in[1];
    const float* Wo   = (const float*)d_in[2];
    const float* sq   = (const float*)d_in[3];
    const float* sk   = (const float*)d_in[4];
    float* out = (float*)d_out;

    float *qkv, *z, *ss, *inv;
    cudaGetSymbolAddress((void**)&qkv, g_qkv);
    cudaGetSymbolAddress((void**)&z,   g_z);
    cudaGetSymbolAddress((void**)&ss,  g_sumsq);
    cudaGetSymbolAddress((void**)&inv, g_inv);

    static bool attr_done = false;
    if (!attr_done) {
        cudaFuncSetAttribute(gemm_mma_kernel, cudaFuncAttributeMaxDynamicSharedMemorySize, GEMM_SMEM);
        cudaFuncSetAttribute(flash_kernel, cudaFuncAttributeMaxDynamicSharedMemorySize, 102400);
        attr_done = true;
    }

    zero2_kernel<<<1, 32>>>(ss);

    gemm_mma_kernel<<<dim3(3 * D_MODEL / 128, MROWS / 128), 256, GEMM_SMEM>>>(
        x, Wqkv, qkv, 3 * D_MODEL, D_MODEL, ss, 1);

    finalize_kernel<<<1, 32>>>(ss, inv);

    flash_kernel<<<dim3(SEQ / 128, NH, BATCH), 256, 102400>>>(qkv, inv, sq, sk, z);

    gemm_mma_kernel<<<dim3(D_MODEL / 128, MROWS / 128), 256, GEMM_SMEM>>>(
        z, Wo, out, D_MODEL, D_MODEL, nullptr, 0);
}

// round 6
// speedup vs baseline: 1.2792x; 1.1186x over previous
#include <cuda_runtime.h>
#include <math.h>
#include <stdint.h>

#define D_MODEL 1024
#define NH 16
#define DH 64
#define BATCH 4
#define SEQ 1024
#define MROWS (BATCH*SEQ)        // 4096
#define QK_COUNT 4194304.0f
#define EPS 1e-6f

typedef unsigned long long ull;

// ---------------- scratch ---------------------------------------------------
__device__ float g_qkv[MROWS * 3 * D_MODEL];
__device__ float g_z[MROWS * D_MODEL];
__device__ float g_sumsq[2];
__device__ float g_inv[2];

// ---------------- tiny kernels ----------------------------------------------
__global__ void zero2_kernel(float* p) { if (threadIdx.x < 2) p[threadIdx.x] = 0.0f; }

__global__ void finalize_kernel(const float* __restrict__ ss, float* __restrict__ inv) {
    if (threadIdx.x < 2) {
        float rms = sqrtf(ss[threadIdx.x] / QK_COUNT);
        inv[threadIdx.x] = 1.0f / (rms + EPS);
    }
}

// ---------------- packed f32x2 helpers ----------------------------------------
__device__ __forceinline__ ull dup2(float x) {
    ull r; asm("mov.b64 %0, {%1, %1};" : "=l"(r) : "f"(x)); return r;
}
__device__ __forceinline__ void fma2(ull& d, ull a, ull b) {
    asm("fma.rn.f32x2 %0, %1, %2, %0;" : "+l"(d) : "l"(a), "l"(b));
}
__device__ __forceinline__ void mul2(ull& d, ull a) {
    asm("mul.rn.f32x2 %0, %0, %1;" : "+l"(d) : "l"(a));
}
__device__ __forceinline__ float2 unpk(ull v) {
    float2 f; asm("mov.b64 {%0, %1}, %2;" : "=f"(f.x), "=f"(f.y) : "l"(v)); return f;
}

// ---------------- f32x2 SGEMM: C[M,N] = A[M,K] @ B[K,N] ------------------------
// 128x128 block, BK=16, 256 threads, 8x8 microtile held as 8x4 packed pairs.
// Global loads of tile t+1 issued before compute of tile t (hidden under FMA).
__global__ __launch_bounds__(256)
void sgemm2_kernel(const float* __restrict__ A, const float* __restrict__ B,
                   float* __restrict__ C, int N, int K,
                   float* sumsq, int do_sumsq)
{
    __shared__ __align__(16) float As[16][128];   // [k][m]
    __shared__ __align__(16) float Bs[16][128];   // [k][n]
    __shared__ float red[256];

    const int tid  = threadIdx.x;
    const int bcol = blockIdx.x;
    const int brow = blockIdx.y;
    const int trow = (tid >> 4) * 8;
    const int tcol = (tid & 15) * 8;

    const float* Ab = A + (size_t)brow * 128 * K;
    const float* Bb = B + (size_t)bcol * 128;
    const int KT = K / 16;

    ull acc[8][4];
#pragma unroll
    for (int i = 0; i < 8; i++)
#pragma unroll
        for (int j = 0; j < 4; j++) acc[i][j] = 0ULL;

    // per-thread load coords (2 float4 each for A and B per tile)
    const int ar0 = tid >> 2;            // +64 per l
    const int ak  = (tid & 3) * 4;
    const int br0 = tid >> 5;            // +8 per l
    const int bc  = (tid & 31) * 4;

    float4 ra[2], rb[2];
    auto ldg_tile = [&](int k0) {
#pragma unroll
        for (int l = 0; l < 2; l++)
            ra[l] = *(const float4*)(Ab + (size_t)(ar0 + l * 64) * K + k0 + ak);
#pragma unroll
        for (int l = 0; l < 2; l++)
            rb[l] = *(const float4*)(Bb + (size_t)(k0 + br0 + l * 8) * N + bc);
    };
    auto sts_tile = [&]() {
#pragma unroll
        for (int l = 0; l < 2; l++) {
            int r = ar0 + l * 64;
            As[ak + 0][r] = ra[l].x;
            As[ak + 1][r] = ra[l].y;
            As[ak + 2][r] = ra[l].z;
            As[ak + 3][r] = ra[l].w;
            *(float4*)(&Bs[br0 + l * 8][bc]) = rb[l];
        }
    };

    ldg_tile(0);
    sts_tile();

    for (int t = 0; t < KT; t++) {
        if (t + 1 < KT) ldg_tile((t + 1) * 16);
        __syncthreads();

#pragma unroll
        for (int kk = 0; kk < 16; kk++) {
            float4 a0 = *(const float4*)&As[kk][trow];
            float4 a1 = *(const float4*)&As[kk][trow + 4];
            ulonglong2 b0 = *(const ulonglong2*)&Bs[kk][tcol];
            ulonglong2 b1 = *(const ulonglong2*)&Bs[kk][tcol + 4];
            ull ad[8] = {dup2(a0.x), dup2(a0.y), dup2(a0.z), dup2(a0.w),
                         dup2(a1.x), dup2(a1.y), dup2(a1.z), dup2(a1.w)};
            ull bd[4] = {b0.x, b0.y, b1.x, b1.y};
#pragma unroll
            for (int i = 0; i < 8; i++)
#pragma unroll
                for (int j = 0; j < 4; j++)
                    fma2(acc[i][j], ad[i], bd[j]);
        }
        __syncthreads();
        if (t + 1 < KT) sts_tile();
    }

    // ---- epilogue: store + fused q/k sum-of-squares ----
    float* Cb = C + (size_t)brow * 128 * N + (size_t)bcol * 128;
    const int colbase = bcol * 128;
    float ss = 0.0f;
#pragma unroll
    for (int i = 0; i < 8; i++) {
        float2 v0 = unpk(acc[i][0]), v1 = unpk(acc[i][1]);
        float2 v2 = unpk(acc[i][2]), v3 = unpk(acc[i][3]);
        float4 c0 = {v0.x, v0.y, v1.x, v1.y};
        float4 c1 = {v2.x, v2.y, v3.x, v3.y};
        *(float4*)(Cb + (size_t)(trow + i) * N + tcol)     = c0;
        *(float4*)(Cb + (size_t)(trow + i) * N + tcol + 4) = c1;
        if (do_sumsq && colbase < 2048)
            ss += c0.x*c0.x + c0.y*c0.y + c0.z*c0.z + c0.w*c0.w
                + c1.x*c1.x + c1.y*c1.y + c1.z*c1.z + c1.w*c1.w;
    }

    if (do_sumsq && colbase < 2048) {
        red[tid] = ss;
        __syncthreads();
        for (int s = 128; s > 0; s >>= 1) {
            if (tid < s) red[tid] += red[tid + s];
            __syncthreads();
        }
        if (tid == 0) atomicAdd(&sumsq[colbase < 1024 ? 0 : 1], red[0]);
    }
}

// ---------------- Flash attention with f32x2 inner loops ----------------------
__global__ __launch_bounds__(256)
void flash_kernel(const float* __restrict__ qkv, const float* __restrict__ inv,
                  const float* __restrict__ scale_q, const float* __restrict__ scale_k,
                  float* __restrict__ z)
{
    extern __shared__ float sm[];
    float* Qst = sm;                    // [d][r]  stride 132
    float* Kst = Qst + 64 * 132;        // [d][c]  stride 68
    float* Vs  = Kst + 64 * 68;         // [j][c]  stride 68
    float* Pst = Vs  + 64 * 68;         // [j][r]  stride 132

    const int tid = threadIdx.x;
    const int qt  = blockIdx.x;
    const int h   = blockIdx.y;
    const int b   = blockIdx.z;
    const int trow = (tid >> 4) * 8;
    const int tcol = (tid & 15) * 4;

    const float invq = inv[0];
    const float invk = inv[1];

    {
        const int base = b * SEQ + qt * 128;
#pragma unroll
        for (int l = 0; l < 8; l++) {
            int idx = tid + l * 256;
            int r   = idx >> 4;
            int d   = (idx & 15) * 4;
            float4 v = *(const float4*)(qkv + (size_t)(base + r) * 3072 + h * DH + d);
            Qst[(d + 0) * 132 + r] = v.x * invq * scale_q[d + 0];
            Qst[(d + 1) * 132 + r] = v.y * invq * scale_q[d + 1];
            Qst[(d + 2) * 132 + r] = v.z * invq * scale_q[d + 2];
            Qst[(d + 3) * 132 + r] = v.w * invq * scale_q[d + 3];
        }
    }

    ull o2[8][2];
    float mrow[8], lrow[8];
#pragma unroll
    for (int i = 0; i < 8; i++) {
        mrow[i] = -INFINITY; lrow[i] = 0.0f;
        o2[i][0] = 0ULL; o2[i][1] = 0ULL;
    }

    for (int t = 0; t < 16; t++) {
        __syncthreads();
#pragma unroll
        for (int u = 0; u < 4; u++) {
            int idx = tid + u * 256;
            int c   = idx >> 4;
            int d   = (idx & 15) * 4;
            int srow = b * SEQ + t * 64 + c;
            float4 kv = *(const float4*)(qkv + (size_t)srow * 3072 + 1024 + h * DH + d);
            Kst[(d + 0) * 68 + c] = kv.x * invk * scale_k[d + 0];
            Kst[(d + 1) * 68 + c] = kv.y * invk * scale_k[d + 1];
            Kst[(d + 2) * 68 + c] = kv.z * invk * scale_k[d + 2];
            Kst[(d + 3) * 68 + c] = kv.w * invk * scale_k[d + 3];
            float4 vv = *(const float4*)(qkv + (size_t)srow * 3072 + 2048 + h * DH + d);
            *(float4*)&Vs[c * 68 + d] = vv;
        }
        __syncthreads();

        // ---- S = Q' @ K'^T (packed pairs over kv columns) ----
        ull s2[8][2];
#pragma unroll
        for (int i = 0; i < 8; i++) { s2[i][0] = 0ULL; s2[i][1] = 0ULL; }

#pragma unroll 8
        for (int d = 0; d < 64; d++) {
            float4 a0 = *(const float4*)&Qst[d * 132 + trow];
            float4 a1 = *(const float4*)&Qst[d * 132 + trow + 4];
            ulonglong2 bb = *(const ulonglong2*)&Kst[d * 68 + tcol];
            ull ad[8] = {dup2(a0.x), dup2(a0.y), dup2(a0.z), dup2(a0.w),
                         dup2(a1.x), dup2(a1.y), dup2(a1.z), dup2(a1.w)};
#pragma unroll
            for (int i = 0; i < 8; i++) {
                fma2(s2[i][0], ad[i], bb.x);
                fma2(s2[i][1], ad[i], bb.y);
            }
        }

        // ---- online softmax update; write P (kv-major) ----
#pragma unroll
        for (int i = 0; i < 8; i++) {
            float2 sa = unpk(s2[i][0]);
            float2 sb = unpk(s2[i][1]);
            float tmax = fmaxf(fmaxf(sa.x, sa.y), fmaxf(sb.x, sb.y));
#pragma unroll
            for (int off = 8; off >= 1; off >>= 1)
                tmax = fmaxf(tmax, __shfl_xor_sync(0xffffffffu, tmax, off));
            float mnew = fmaxf(mrow[i], tmax);
            float corr = __expf(mrow[i] - mnew);
            float p0 = __expf(sa.x - mnew);
            float p1 = __expf(sa.y - mnew);
            float p2 = __expf(sb.x - mnew);
            float p3 = __expf(sb.y - mnew);
            Pst[(tcol + 0) * 132 + (trow + i)] = p0;
            Pst[(tcol + 1) * 132 + (trow + i)] = p1;
            Pst[(tcol + 2) * 132 + (trow + i)] = p2;
            Pst[(tcol + 3) * 132 + (trow + i)] = p3;
            float psum = p0 + p1 + p2 + p3;
#pragma unroll
            for (int off = 8; off >= 1; off >>= 1)
                psum += __shfl_xor_sync(0xffffffffu, psum, off);
            lrow[i] = lrow[i] * corr + psum;
            mrow[i] = mnew;
            ull cd = dup2(corr);
            mul2(o2[i][0], cd);
            mul2(o2[i][1], cd);
        }
        __syncthreads();

        // ---- O += P @ V (packed pairs over head-dim columns) ----
#pragma unroll 8
        for (int j = 0; j < 64; j++) {
            float4 p0 = *(const float4*)&Pst[j * 132 + trow];
            float4 p1 = *(const float4*)&Pst[j * 132 + trow + 4];
            ulonglong2 vv = *(const ulonglong2*)&Vs[j * 68 + tcol];
            ull pd[8] = {dup2(p0.x), dup2(p0.y), dup2(p0.z), dup2(p0.w),
                         dup2(p1.x), dup2(p1.y), dup2(p1.z), dup2(p1.w)};
#pragma unroll
            for (int i = 0; i < 8; i++) {
                fma2(o2[i][0], pd[i], vv.x);
                fma2(o2[i][1], pd[i], vv.y);
            }
        }
    }

    // ---- epilogue: z = O / l ----
#pragma unroll
    for (int i = 0; i < 8; i++) {
        float rl = 1.0f / lrow[i];
        float2 oa = unpk(o2[i][0]);
        float2 ob = unpk(o2[i][1]);
        float4 out = {oa.x * rl, oa.y * rl, ob.x * rl, ob.y * rl};
        int row = b * SEQ + qt * 128 + trow + i;
        *(float4*)(z + (size_t)row * D_MODEL + h * DH + tcol) = out;
    }
}

// ---------------- launcher ------------------------------------------------------
extern "C" void kernel_launch(void* const* d_in, const int* in_sizes, int n_in,
                              void* d_out, int out_size)
{
    const float* x    = (const float*)d_in[0];
    const float* Wqkv = (const float*)d_in[1];
    const float* Wo   = (const float*)d_in[2];
    const float* sq   = (const float*)d_in[3];
    const float* sk   = (const float*)d_in[4];
    float* out = (float*)d_out;

    float *qkv, *z, *ss, *inv;
    cudaGetSymbolAddress((void**)&qkv, g_qkv);
    cudaGetSymbolAddress((void**)&z,   g_z);
    cudaGetSymbolAddress((void**)&ss,  g_sumsq);
    cudaGetSymbolAddress((void**)&inv, g_inv);

    static bool attr_done = false;
    if (!attr_done) {
        cudaFuncSetAttribute(flash_kernel, cudaFuncAttributeMaxDynamicSharedMemorySize, 102400);
        attr_done = true;
    }

    zero2_kernel<<<1, 32>>>(ss);

    sgemm2_kernel<<<dim3(3 * D_MODEL / 128, MROWS / 128), 256>>>(
        x, Wqkv, qkv, 3 * D_MODEL, D_MODEL, ss, 1);

    finalize_kernel<<<1, 32>>>(ss, inv);

    flash_kernel<<<dim3(SEQ / 128, NH, BATCH), 256, 102400>>>(qkv, inv, sq, sk, z);

    sgemm2_kernel<<<dim3(D_MODEL / 128, MROWS / 128), 256>>>(
        z, Wo, out, D_MODEL, D_MODEL, nullptr, 0);
}

// round 7
// speedup vs baseline: 1.4385x; 1.1245x over previous
#include <cuda_runtime.h>
#include <math.h>
#include <stdint.h>

#define D_MODEL 1024
#define NH 16
#define DH 64
#define BATCH 4
#define SEQ 1024
#define MROWS (BATCH*SEQ)        // 4096
#define QK_COUNT 4194304.0f
#define EPS 1e-6f

typedef unsigned long long ull;

// ---------------- scratch ---------------------------------------------------
__device__ float g_qkv[MROWS * 3 * D_MODEL];
__device__ float g_z[MROWS * D_MODEL];
__device__ float g_sumsq[2];
__device__ float g_inv[2];

// ---------------- tiny kernels ----------------------------------------------
__global__ void zero2_kernel(float* p) { if (threadIdx.x < 2) p[threadIdx.x] = 0.0f; }

__global__ void finalize_kernel(const float* __restrict__ ss, float* __restrict__ inv) {
    if (threadIdx.x < 2) {
        float rms = sqrtf(ss[threadIdx.x] / QK_COUNT);
        inv[threadIdx.x] = 1.0f / (rms + EPS);
    }
}

// ---------------- packed f32x2 helpers ----------------------------------------
__device__ __forceinline__ ull dup2(float x) {
    ull r; asm("mov.b64 %0, {%1, %1};" : "=l"(r) : "f"(x)); return r;
}
__device__ __forceinline__ ull pack2f(float a, float b) {
    ull r; asm("mov.b64 %0, {%1, %2};" : "=l"(r) : "f"(a), "f"(b)); return r;
}
__device__ __forceinline__ void fma2(ull& d, ull a, ull b) {
    asm("fma.rn.f32x2 %0, %1, %2, %0;" : "+l"(d) : "l"(a), "l"(b));
}
__device__ __forceinline__ void mul2(ull& d, ull a) {
    asm("mul.rn.f32x2 %0, %0, %1;" : "+l"(d) : "l"(a));
}
__device__ __forceinline__ float2 unpk(ull v) {
    float2 f; asm("mov.b64 {%0, %1}, %2;" : "=f"(f.x), "=f"(f.y) : "l"(v)); return f;
}

// ---------------- f32x2 SGEMM: C[M,N] = A[M,K] @ B[K,N] ------------------------
// 128x128 block, BK=16, 256 threads, microtile 8 rows x {4 cols @tcol1, 4 cols
// @tcol1+64}. Double-buffered smem, ONE sync per k-tile, LDG for t+1 issued
// before compute of t. B fragment loads are conflict-free (16B lane stride).
__global__ __launch_bounds__(256, 2)
void sgemm2_kernel(const float* __restrict__ A, const float* __restrict__ B,
                   float* __restrict__ C, int N, int K,
                   float* sumsq, int do_sumsq)
{
    __shared__ __align__(16) float As[2][16][128];   // [stage][k][m]
    __shared__ __align__(16) float Bs[2][16][128];   // [stage][k][n]
    __shared__ float red[256];

    const int tid  = threadIdx.x;
    const int bcol = blockIdx.x;
    const int brow = blockIdx.y;
    const int trow  = (tid >> 4) * 8;     // 0..120
    const int tcol1 = (tid & 15) * 4;     // 0..60

    const float* Ab = A + (size_t)brow * 128 * K;
    const float* Bb = B + (size_t)bcol * 128;
    const int KT = K / 16;

    ull acc[8][4];
#pragma unroll
    for (int i = 0; i < 8; i++)
#pragma unroll
        for (int j = 0; j < 4; j++) acc[i][j] = 0ULL;

    const int ar0 = tid >> 2;            // +64 per l
    const int ak  = (tid & 3) * 4;
    const int br0 = tid >> 5;            // +8 per l
    const int bc  = (tid & 31) * 4;

    float4 ra[2], rb[2];
    auto ldg_tile = [&](int k0) {
#pragma unroll
        for (int l = 0; l < 2; l++)
            ra[l] = *(const float4*)(Ab + (size_t)(ar0 + l * 64) * K + k0 + ak);
#pragma unroll
        for (int l = 0; l < 2; l++)
            rb[l] = *(const float4*)(Bb + (size_t)(k0 + br0 + l * 8) * N + bc);
    };
    auto sts_tile = [&](int st) {
#pragma unroll
        for (int l = 0; l < 2; l++) {
            int r = ar0 + l * 64;
            As[st][ak + 0][r] = ra[l].x;
            As[st][ak + 1][r] = ra[l].y;
            As[st][ak + 2][r] = ra[l].z;
            As[st][ak + 3][r] = ra[l].w;
            *(float4*)(&Bs[st][br0 + l * 8][bc]) = rb[l];
        }
    };

    ldg_tile(0);
    sts_tile(0);

    for (int t = 0; t < KT; t++) {
        const int s = t & 1;
        __syncthreads();
        if (t + 1 < KT) ldg_tile((t + 1) * 16);

#pragma unroll
        for (int kk = 0; kk < 16; kk++) {
            float4 a0 = *(const float4*)&As[s][kk][trow];
            float4 a1 = *(const float4*)&As[s][kk][trow + 4];
            ulonglong2 b0 = *(const ulonglong2*)&Bs[s][kk][tcol1];        // cols tcol1..+3
            ulonglong2 b1 = *(const ulonglong2*)&Bs[s][kk][tcol1 + 64];   // cols 64+tcol1..+3
            ull ad[8] = {dup2(a0.x), dup2(a0.y), dup2(a0.z), dup2(a0.w),
                         dup2(a1.x), dup2(a1.y), dup2(a1.z), dup2(a1.w)};
#pragma unroll
            for (int i = 0; i < 8; i++) {
                fma2(acc[i][0], ad[i], b0.x);
                fma2(acc[i][1], ad[i], b0.y);
                fma2(acc[i][2], ad[i], b1.x);
                fma2(acc[i][3], ad[i], b1.y);
            }
        }
        if (t + 1 < KT) sts_tile(s ^ 1);
    }

    // ---- epilogue: store + fused q/k sum-of-squares ----
    float* Cb = C + (size_t)brow * 128 * N + (size_t)bcol * 128;
    const int colbase = bcol * 128;
    float ss = 0.0f;
#pragma unroll
    for (int i = 0; i < 8; i++) {
        float2 v0 = unpk(acc[i][0]), v1 = unpk(acc[i][1]);
        float2 v2 = unpk(acc[i][2]), v3 = unpk(acc[i][3]);
        float4 c0 = {v0.x, v0.y, v1.x, v1.y};
        float4 c1 = {v2.x, v2.y, v3.x, v3.y};
        *(float4*)(Cb + (size_t)(trow + i) * N + tcol1)      = c0;
        *(float4*)(Cb + (size_t)(trow + i) * N + tcol1 + 64) = c1;
        if (do_sumsq && colbase < 2048)
            ss += c0.x*c0.x + c0.y*c0.y + c0.z*c0.z + c0.w*c0.w
                + c1.x*c1.x + c1.y*c1.y + c1.z*c1.z + c1.w*c1.w;
    }

    if (do_sumsq && colbase < 2048) {
        red[tid] = ss;
        __syncthreads();
        for (int s2 = 128; s2 > 0; s2 >>= 1) {
            if (tid < s2) red[tid] += red[tid + s2];
            __syncthreads();
        }
        if (tid == 0) atomicAdd(&sumsq[colbase < 1024 ? 0 : 1], red[0]);
    }
}

// ---------------- Flash attention, row-packed f32x2 inner loops ---------------
// acc pairs along the q-row axis: Q/P pairs load packed from smem (ulonglong2),
// only the K/V side needs dup (4 per d-step). 23 issue slots per d-step.
__global__ __launch_bounds__(256, 2)
void flash_kernel(const float* __restrict__ qkv, const float* __restrict__ inv,
                  const float* __restrict__ scale_q, const float* __restrict__ scale_k,
                  float* __restrict__ z)
{
    extern __shared__ float sm[];
    float* Qst = sm;                    // [d][r]  stride 132
    float* Kst = Qst + 64 * 132;        // [d][c]  stride 68
    float* Vs  = Kst + 64 * 68;         // [j][c]  stride 68
    float* Pst = Vs  + 64 * 68;         // [j][r]  stride 132

    const int tid = threadIdx.x;
    const int qt  = blockIdx.x;
    const int h   = blockIdx.y;
    const int b   = blockIdx.z;
    const int trow = (tid >> 4) * 8;
    const int tcol = (tid & 15) * 4;

    const float invq = inv[0];
    const float invk = inv[1];

    {
        const int base = b * SEQ + qt * 128;
#pragma unroll
        for (int l = 0; l < 8; l++) {
            int idx = tid + l * 256;
            int r   = idx >> 4;
            int d   = (idx & 15) * 4;
            float4 v = *(const float4*)(qkv + (size_t)(base + r) * 3072 + h * DH + d);
            Qst[(d + 0) * 132 + r] = v.x * invq * scale_q[d + 0];
            Qst[(d + 1) * 132 + r] = v.y * invq * scale_q[d + 1];
            Qst[(d + 2) * 132 + r] = v.z * invq * scale_q[d + 2];
            Qst[(d + 3) * 132 + r] = v.w * invq * scale_q[d + 3];
        }
    }

    // o2[rp][c] = (O[trow+2rp][tcol+c], O[trow+2rp+1][tcol+c])
    ull o2[4][4];
    float mrow[8], lrow[8];
#pragma unroll
    for (int i = 0; i < 8; i++) { mrow[i] = -INFINITY; lrow[i] = 0.0f; }
#pragma unroll
    for (int rp = 0; rp < 4; rp++)
#pragma unroll
        for (int c = 0; c < 4; c++) o2[rp][c] = 0ULL;

    for (int t = 0; t < 16; t++) {
        __syncthreads();
#pragma unroll
        for (int u = 0; u < 4; u++) {
            int idx = tid + u * 256;
            int c   = idx >> 4;
            int d   = (idx & 15) * 4;
            int srow = b * SEQ + t * 64 + c;
            float4 kv = *(const float4*)(qkv + (size_t)srow * 3072 + 1024 + h * DH + d);
            Kst[(d + 0) * 68 + c] = kv.x * invk * scale_k[d + 0];
            Kst[(d + 1) * 68 + c] = kv.y * invk * scale_k[d + 1];
            Kst[(d + 2) * 68 + c] = kv.z * invk * scale_k[d + 2];
            Kst[(d + 3) * 68 + c] = kv.w * invk * scale_k[d + 3];
            float4 vv = *(const float4*)(qkv + (size_t)srow * 3072 + 2048 + h * DH + d);
            *(float4*)&Vs[c * 68 + d] = vv;
        }
        __syncthreads();

        // ---- S = Q' @ K'^T, row-pair packed ----
        ull s2[4][4];
#pragma unroll
        for (int rp = 0; rp < 4; rp++)
#pragma unroll
            for (int c = 0; c < 4; c++) s2[rp][c] = 0ULL;

#pragma unroll 8
        for (int d = 0; d < 64; d++) {
            ulonglong2 q01 = *(const ulonglong2*)&Qst[d * 132 + trow];      // rows (0,1),(2,3)
            ulonglong2 q23 = *(const ulonglong2*)&Qst[d * 132 + trow + 4];  // rows (4,5),(6,7)
            float4 kv = *(const float4*)&Kst[d * 68 + tcol];
            ull kd[4] = {dup2(kv.x), dup2(kv.y), dup2(kv.z), dup2(kv.w)};
#pragma unroll
            for (int c = 0; c < 4; c++) {
                fma2(s2[0][c], q01.x, kd[c]);
                fma2(s2[1][c], q01.y, kd[c]);
                fma2(s2[2][c], q23.x, kd[c]);
                fma2(s2[3][c], q23.y, kd[c]);
            }
        }

        // ---- online softmax per row-pair; write P as row-pair float2 ----
#pragma unroll
        for (int rp = 0; rp < 4; rp++) {
            float2 c0 = unpk(s2[rp][0]);
            float2 c1 = unpk(s2[rp][1]);
            float2 c2 = unpk(s2[rp][2]);
            float2 c3 = unpk(s2[rp][3]);
            const int ia = 2 * rp, ib = 2 * rp + 1;

            float ta = fmaxf(fmaxf(c0.x, c1.x), fmaxf(c2.x, c3.x));
            float tb = fmaxf(fmaxf(c0.y, c1.y), fmaxf(c2.y, c3.y));
#pragma unroll
            for (int off = 8; off >= 1; off >>= 1) {
                ta = fmaxf(ta, __shfl_xor_sync(0xffffffffu, ta, off));
                tb = fmaxf(tb, __shfl_xor_sync(0xffffffffu, tb, off));
            }
            float ma = fmaxf(mrow[ia], ta);
            float mb = fmaxf(mrow[ib], tb);
            float corra = __expf(mrow[ia] - ma);
            float corrb = __expf(mrow[ib] - mb);

            float pa0 = __expf(c0.x - ma), pb0 = __expf(c0.y - mb);
            float pa1 = __expf(c1.x - ma), pb1 = __expf(c1.y - mb);
            float pa2 = __expf(c2.x - ma), pb2 = __expf(c2.y - mb);
            float pa3 = __expf(c3.x - ma), pb3 = __expf(c3.y - mb);

            *(float2*)&Pst[(tcol + 0) * 132 + trow + 2 * rp] = make_float2(pa0, pb0);
            *(float2*)&Pst[(tcol + 1) * 132 + trow + 2 * rp] = make_float2(pa1, pb1);
            *(float2*)&Pst[(tcol + 2) * 132 + trow + 2 * rp] = make_float2(pa2, pb2);
            *(float2*)&Pst[(tcol + 3) * 132 + trow + 2 * rp] = make_float2(pa3, pb3);

            float psa = pa0 + pa1 + pa2 + pa3;
            float psb = pb0 + pb1 + pb2 + pb3;
#pragma unroll
            for (int off = 8; off >= 1; off >>= 1) {
                psa += __shfl_xor_sync(0xffffffffu, psa, off);
                psb += __shfl_xor_sync(0xffffffffu, psb, off);
            }
            lrow[ia] = lrow[ia] * corra + psa;
            lrow[ib] = lrow[ib] * corrb + psb;
            mrow[ia] = ma;
            mrow[ib] = mb;

            ull cp = pack2f(corra, corrb);
#pragma unroll
            for (int c = 0; c < 4; c++) mul2(o2[rp][c], cp);
        }
        __syncthreads();

        // ---- O += P @ V, row-pair packed ----
#pragma unroll 8
        for (int j = 0; j < 64; j++) {
            ulonglong2 p01 = *(const ulonglong2*)&Pst[j * 132 + trow];
            ulonglong2 p23 = *(const ulonglong2*)&Pst[j * 132 + trow + 4];
            float4 vv = *(const float4*)&Vs[j * 68 + tcol];
            ull vd[4] = {dup2(vv.x), dup2(vv.y), dup2(vv.z), dup2(vv.w)};
#pragma unroll
            for (int c = 0; c < 4; c++) {
                fma2(o2[0][c], p01.x, vd[c]);
                fma2(o2[1][c], p01.y, vd[c]);
                fma2(o2[2][c], p23.x, vd[c]);
                fma2(o2[3][c], p23.y, vd[c]);
            }
        }
    }

    // ---- epilogue: z = O / l ----
#pragma unroll
    for (int rp = 0; rp < 4; rp++) {
        float2 c0 = unpk(o2[rp][0]);
        float2 c1 = unpk(o2[rp][1]);
        float2 c2 = unpk(o2[rp][2]);
        float2 c3 = unpk(o2[rp][3]);
        const int ia = 2 * rp, ib = 2 * rp + 1;
        float rla = 1.0f / lrow[ia];
        float rlb = 1.0f / lrow[ib];
        int rowa = b * SEQ + qt * 128 + trow + ia;
        int rowb = rowa + 1;
        float4 outa = {c0.x * rla, c1.x * rla, c2.x * rla, c3.x * rla};
        float4 outb = {c0.y * rlb, c1.y * rlb, c2.y * rlb, c3.y * rlb};
        *(float4*)(z + (size_t)rowa * D_MODEL + h * DH + tcol) = outa;
        *(float4*)(z + (size_t)rowb * D_MODEL + h * DH + tcol) = outb;
    }
}

// ---------------- launcher ------------------------------------------------------
extern "C" void kernel_launch(void* const* d_in, const int* in_sizes, int n_in,
                              void* d_out, int out_size)
{
    const float* x    = (const float*)d_in[0];
    const float* Wqkv = (const float*)d_in[1];
    const float* Wo   = (const float*)d_in[2];
    const float* sq   = (const float*)d_in[3];
    const float* sk   = (const float*)d_in[4];
    float* out = (float*)d_out;

    float *qkv, *z, *ss, *inv;
    cudaGetSymbolAddress((void**)&qkv, g_qkv);
    cudaGetSymbolAddress((void**)&z,   g_z);
    cudaGetSymbolAddress((void**)&ss,  g_sumsq);
    cudaGetSymbolAddress((void**)&inv, g_inv);

    static bool attr_done = false;
    if (!attr_done) {
        cudaFuncSetAttribute(flash_kernel, cudaFuncAttributeMaxDynamicSharedMemorySize, 102400);
        attr_done = true;
    }

    zero2_kernel<<<1, 32>>>(ss);

    sgemm2_kernel<<<dim3(3 * D_MODEL / 128, MROWS / 128), 256>>>(
        x, Wqkv, qkv, 3 * D_MODEL, D_MODEL, ss, 1);

    finalize_kernel<<<1, 32>>>(ss, inv);

    flash_kernel<<<dim3(SEQ / 128, NH, BATCH), 256, 102400>>>(qkv, inv, sq, sk, z);

    sgemm2_kernel<<<dim3(D_MODEL / 128, MROWS / 128), 256>>>(
        z, Wo, out, D_MODEL, D_MODEL, nullptr, 0);
}

// round 8
// speedup vs baseline: 1.4985x; 1.0418x over previous
#include <cuda_runtime.h>
#include <math.h>
#include <stdint.h>

#define D_MODEL 1024
#define NH 16
#define DH 64
#define BATCH 4
#define SEQ 1024
#define MROWS (BATCH*SEQ)        // 4096
#define QK_COUNT 4194304.0f
#define EPS 1e-6f

typedef unsigned long long ull;

// ---------------- scratch ---------------------------------------------------
__device__ float g_qkv[MROWS * 3 * D_MODEL];   // 48 MB
__device__ float g_z[MROWS * D_MODEL];         // 16 MB
__device__ float g_xt[D_MODEL * MROWS];        // 16 MB  (x^T)
__device__ float g_zt[D_MODEL * MROWS];        // 16 MB  (z^T)
__device__ float g_sumsq[2];
__device__ float g_inv[2];

// ---------------- tiny kernels ----------------------------------------------
__global__ void zero2_kernel(float* p) { if (threadIdx.x < 2) p[threadIdx.x] = 0.0f; }

__global__ void finalize_kernel(const float* __restrict__ ss, float* __restrict__ inv) {
    if (threadIdx.x < 2) {
        float rms = sqrtf(ss[threadIdx.x] / QK_COUNT);
        inv[threadIdx.x] = 1.0f / (rms + EPS);
    }
}

// ---------------- transpose: out[C][R] = in[R][C] -----------------------------
__global__ __launch_bounds__(256)
void transpose_kernel(const float* __restrict__ in, float* __restrict__ out,
                      int R, int C)
{
    __shared__ float tile[32][33];
    const int tx = threadIdx.x & 31;
    const int ty = threadIdx.x >> 5;           // 0..7
    const int bx = blockIdx.x * 32;            // col base
    const int by = blockIdx.y * 32;            // row base
#pragma unroll
    for (int j = 0; j < 32; j += 8)
        tile[ty + j][tx] = in[(size_t)(by + ty + j) * C + bx + tx];
    __syncthreads();
#pragma unroll
    for (int j = 0; j < 32; j += 8)
        out[(size_t)(bx + ty + j) * R + by + tx] = tile[tx][ty + j];
}

// ---------------- packed f32x2 helpers ----------------------------------------
__device__ __forceinline__ ull dup2(float x) {
    ull r; asm("mov.b64 %0, {%1, %1};" : "=l"(r) : "f"(x)); return r;
}
__device__ __forceinline__ ull pack2f(float a, float b) {
    ull r; asm("mov.b64 %0, {%1, %2};" : "=l"(r) : "f"(a), "f"(b)); return r;
}
__device__ __forceinline__ void fma2(ull& d, ull a, ull b) {
    asm("fma.rn.f32x2 %0, %1, %2, %0;" : "+l"(d) : "l"(a), "l"(b));
}
__device__ __forceinline__ void mul2(ull& d, ull a) {
    asm("mul.rn.f32x2 %0, %0, %1;" : "+l"(d) : "l"(a));
}
__device__ __forceinline__ float2 unpk(ull v) {
    float2 f; asm("mov.b64 {%0, %1}, %2;" : "=f"(f.x), "=f"(f.y) : "l"(v)); return f;
}
__device__ __forceinline__ uint32_t smem_u32(const void* p) {
    uint32_t a;
    asm("{ .reg .u64 t; cvta.to.shared.u64 t, %1; cvt.u32.u64 %0, t; }" : "=r"(a) : "l"(p));
    return a;
}
__device__ __forceinline__ void cpa16(uint32_t dst, const void* src) {
    asm volatile("cp.async.ca.shared.global [%0], [%1], 16;" :: "r"(dst), "l"(src));
}
#define CPA_COMMIT() asm volatile("cp.async.commit_group;" ::: "memory")
#define CPA_WAIT1()  asm volatile("cp.async.wait_group 1;" ::: "memory")

// ---------------- cp.async f32x2 GEMM ------------------------------------------
// C[M,N] = A[M,K] @ B[K,N], with At = A^T given ([K][M], stride M).
// Block 128x128, BK=16, 3-stage cp.async ring, 256 threads.
// Row-packed microtile: acc[4 row-pairs][8 cols] (cols tcol..+3, tcol+64..+67).
__global__ __launch_bounds__(256, 2)
void gemm_cpa_kernel(const float* __restrict__ At, const float* __restrict__ B,
                     float* __restrict__ C, int M, int N, int K,
                     float* sumsq, int do_sumsq)
{
    __shared__ __align__(16) float As[3][16][128];
    __shared__ __align__(16) float Bs[3][16][128];
    __shared__ float red[256];

    const int tid  = threadIdx.x;
    const int bcol = blockIdx.x;
    const int brow = blockIdx.y;
    const int trow = (tid >> 4) * 8;     // 0..120
    const int tcol = (tid & 15) * 4;     // 0..60

    const float* Atb = At + brow * 128;            // + k*M walks rows of A^T
    const float* Bb  = B + bcol * 128;
    const int KT = K / 16;

    const uint32_t sA = smem_u32(As);
    const uint32_t sB = smem_u32(Bs);

    // per-thread cp.async chunks: 2 for A, 2 for B (chunk = 16B)
    const int c0 = tid, c1 = tid + 256;
    const int kr0 = c0 >> 5, mo0 = (c0 & 31) * 4;
    const int kr1 = c1 >> 5, mo1 = (c1 & 31) * 4;

    auto issue_tile = [&](int kt, int slot) {
        const uint32_t sa = sA + (uint32_t)slot * 8192;
        const uint32_t sb = sB + (uint32_t)slot * 8192;
        cpa16(sa + (uint32_t)(kr0 * 512 + mo0 * 4), Atb + (size_t)(kt * 16 + kr0) * M + mo0);
        cpa16(sa + (uint32_t)(kr1 * 512 + mo1 * 4), Atb + (size_t)(kt * 16 + kr1) * M + mo1);
        cpa16(sb + (uint32_t)(kr0 * 512 + mo0 * 4), Bb  + (size_t)(kt * 16 + kr0) * N + mo0);
        cpa16(sb + (uint32_t)(kr1 * 512 + mo1 * 4), Bb  + (size_t)(kt * 16 + kr1) * N + mo1);
        CPA_COMMIT();
    };

    ull acc[4][8];
#pragma unroll
    for (int rp = 0; rp < 4; rp++)
#pragma unroll
        for (int j = 0; j < 8; j++) acc[rp][j] = 0ULL;

    issue_tile(0, 0);
    issue_tile(1, 1);

    for (int t = 0; t < KT; t++) {
        const int s = t % 3;
        CPA_WAIT1();                 // tile t landed (tile t+1 may still fly)
        __syncthreads();             // visible to all warps; slot (t+2)%3 free
        const int tn = (t + 2 < KT) ? t + 2 : 0;   // clamp: dummy refetch, keeps wait uniform
        issue_tile(tn, (t + 2) % 3);

#pragma unroll
        for (int kk = 0; kk < 16; kk++) {
            ulonglong2 a01 = *(const ulonglong2*)&As[s][kk][trow];       // rows (0,1),(2,3)
            ulonglong2 a23 = *(const ulonglong2*)&As[s][kk][trow + 4];   // rows (4,5),(6,7)
            float4 b0 = *(const float4*)&Bs[s][kk][tcol];
            float4 b1 = *(const float4*)&Bs[s][kk][tcol + 64];
            ull bd[8] = {dup2(b0.x), dup2(b0.y), dup2(b0.z), dup2(b0.w),
                         dup2(b1.x), dup2(b1.y), dup2(b1.z), dup2(b1.w)};
#pragma unroll
            for (int j = 0; j < 8; j++) {
                fma2(acc[0][j], a01.x, bd[j]);
                fma2(acc[1][j], a01.y, bd[j]);
                fma2(acc[2][j], a23.x, bd[j]);
                fma2(acc[3][j], a23.y, bd[j]);
            }
        }
    }

    // ---- epilogue: store + fused q/k sum-of-squares ----
    const int colbase = bcol * 128;
    float ss = 0.0f;
#pragma unroll
    for (int rp = 0; rp < 4; rp++) {
        float2 u[8];
#pragma unroll
        for (int j = 0; j < 8; j++) u[j] = unpk(acc[rp][j]);
        const int rowa = brow * 128 + trow + 2 * rp;
        float4 a0 = {u[0].x, u[1].x, u[2].x, u[3].x};
        float4 a1 = {u[4].x, u[5].x, u[6].x, u[7].x};
        float4 b0 = {u[0].y, u[1].y, u[2].y, u[3].y};
        float4 b1 = {u[4].y, u[5].y, u[6].y, u[7].y};
        *(float4*)(C + (size_t)rowa * N + colbase + tcol)            = a0;
        *(float4*)(C + (size_t)rowa * N + colbase + tcol + 64)       = a1;
        *(float4*)(C + (size_t)(rowa + 1) * N + colbase + tcol)      = b0;
        *(float4*)(C + (size_t)(rowa + 1) * N + colbase + tcol + 64) = b1;
        if (do_sumsq && colbase < 2048)
            ss += a0.x*a0.x + a0.y*a0.y + a0.z*a0.z + a0.w*a0.w
                + a1.x*a1.x + a1.y*a1.y + a1.z*a1.z + a1.w*a1.w
                + b0.x*b0.x + b0.y*b0.y + b0.z*b0.z + b0.w*b0.w
                + b1.x*b1.x + b1.y*b1.y + b1.z*b1.z + b1.w*b1.w;
    }

    if (do_sumsq && colbase < 2048) {
        red[tid] = ss;
        __syncthreads();
        for (int s2 = 128; s2 > 0; s2 >>= 1) {
            if (tid < s2) red[tid] += red[tid + s2];
            __syncthreads();
        }
        if (tid == 0) atomicAdd(&sumsq[colbase < 1024 ? 0 : 1], red[0]);
    }
}

// ---------------- Flash attention, row-packed f32x2 (scales folded into Q) ----
__global__ __launch_bounds__(256, 2)
void flash_kernel(const float* __restrict__ qkv, const float* __restrict__ inv,
                  const float* __restrict__ scale_q, const float* __restrict__ scale_k,
                  float* __restrict__ z)
{
    extern __shared__ float sm[];
    float* Qst = sm;                    // [d][r]  stride 132 (scaled)
    float* Kst = Qst + 64 * 132;        // [d][c]  stride 68  (raw)
    float* Vs  = Kst + 64 * 68;         // [j][c]  stride 68
    float* Pst = Vs  + 64 * 68;         // [j][r]  stride 132

    const int tid = threadIdx.x;
    const int qt  = blockIdx.x;
    const int h   = blockIdx.y;
    const int b   = blockIdx.z;
    const int trow = (tid >> 4) * 8;
    const int tcol = (tid & 15) * 4;

    const float wsc = inv[0] * inv[1];

    {
        const int base = b * SEQ + qt * 128;
#pragma unroll
        for (int l = 0; l < 8; l++) {
            int idx = tid + l * 256;
            int r   = idx >> 4;
            int d   = (idx & 15) * 4;
            float4 v = *(const float4*)(qkv + (size_t)(base + r) * 3072 + h * DH + d);
            Qst[(d + 0) * 132 + r] = v.x * wsc * scale_q[d + 0] * scale_k[d + 0];
            Qst[(d + 1) * 132 + r] = v.y * wsc * scale_q[d + 1] * scale_k[d + 1];
            Qst[(d + 2) * 132 + r] = v.z * wsc * scale_q[d + 2] * scale_k[d + 2];
            Qst[(d + 3) * 132 + r] = v.w * wsc * scale_q[d + 3] * scale_k[d + 3];
        }
    }

    ull o2[4][4];
    float mrow[8], lrow[8];
#pragma unroll
    for (int i = 0; i < 8; i++) { mrow[i] = -INFINITY; lrow[i] = 0.0f; }
#pragma unroll
    for (int rp = 0; rp < 4; rp++)
#pragma unroll
        for (int c = 0; c < 4; c++) o2[rp][c] = 0ULL;

    for (int t = 0; t < 16; t++) {
        __syncthreads();
#pragma unroll
        for (int u = 0; u < 4; u++) {
            int idx = tid + u * 256;
            int c   = idx >> 4;
            int d   = (idx & 15) * 4;
            int srow = b * SEQ + t * 64 + c;
            float4 kv = *(const float4*)(qkv + (size_t)srow * 3072 + 1024 + h * DH + d);
            Kst[(d + 0) * 68 + c] = kv.x;
            Kst[(d + 1) * 68 + c] = kv.y;
            Kst[(d + 2) * 68 + c] = kv.z;
            Kst[(d + 3) * 68 + c] = kv.w;
            float4 vv = *(const float4*)(qkv + (size_t)srow * 3072 + 2048 + h * DH + d);
            *(float4*)&Vs[c * 68 + d] = vv;
        }
        __syncthreads();

        ull s2[4][4];
#pragma unroll
        for (int rp = 0; rp < 4; rp++)
#pragma unroll
            for (int c = 0; c < 4; c++) s2[rp][c] = 0ULL;

#pragma unroll 8
        for (int d = 0; d < 64; d++) {
            ulonglong2 q01 = *(const ulonglong2*)&Qst[d * 132 + trow];
            ulonglong2 q23 = *(const ulonglong2*)&Qst[d * 132 + trow + 4];
            float4 kv = *(const float4*)&Kst[d * 68 + tcol];
            ull kd[4] = {dup2(kv.x), dup2(kv.y), dup2(kv.z), dup2(kv.w)};
#pragma unroll
            for (int c = 0; c < 4; c++) {
                fma2(s2[0][c], q01.x, kd[c]);
                fma2(s2[1][c], q01.y, kd[c]);
                fma2(s2[2][c], q23.x, kd[c]);
                fma2(s2[3][c], q23.y, kd[c]);
            }
        }

#pragma unroll
        for (int rp = 0; rp < 4; rp++) {
            float2 c0 = unpk(s2[rp][0]);
            float2 c1 = unpk(s2[rp][1]);
            float2 c2 = unpk(s2[rp][2]);
            float2 c3 = unpk(s2[rp][3]);
            const int ia = 2 * rp, ib = 2 * rp + 1;

            float ta = fmaxf(fmaxf(c0.x, c1.x), fmaxf(c2.x, c3.x));
            float tb = fmaxf(fmaxf(c0.y, c1.y), fmaxf(c2.y, c3.y));
#pragma unroll
            for (int off = 8; off >= 1; off >>= 1) {
                ta = fmaxf(ta, __shfl_xor_sync(0xffffffffu, ta, off));
                tb = fmaxf(tb, __shfl_xor_sync(0xffffffffu, tb, off));
            }
            float ma = fmaxf(mrow[ia], ta);
            float mb = fmaxf(mrow[ib], tb);
            float corra = __expf(mrow[ia] - ma);
            float corrb = __expf(mrow[ib] - mb);

            float pa0 = __expf(c0.x - ma), pb0 = __expf(c0.y - mb);
            float pa1 = __expf(c1.x - ma), pb1 = __expf(c1.y - mb);
            float pa2 = __expf(c2.x - ma), pb2 = __expf(c2.y - mb);
            float pa3 = __expf(c3.x - ma), pb3 = __expf(c3.y - mb);

            *(float2*)&Pst[(tcol + 0) * 132 + trow + 2 * rp] = make_float2(pa0, pb0);
            *(float2*)&Pst[(tcol + 1) * 132 + trow + 2 * rp] = make_float2(pa1, pb1);
            *(float2*)&Pst[(tcol + 2) * 132 + trow + 2 * rp] = make_float2(pa2, pb2);
            *(float2*)&Pst[(tcol + 3) * 132 + trow + 2 * rp] = make_float2(pa3, pb3);

            float psa = pa0 + pa1 + pa2 + pa3;
            float psb = pb0 + pb1 + pb2 + pb3;
#pragma unroll
            for (int off = 8; off >= 1; off >>= 1) {
                psa += __shfl_xor_sync(0xffffffffu, psa, off);
                psb += __shfl_xor_sync(0xffffffffu, psb, off);
            }
            lrow[ia] = lrow[ia] * corra + psa;
            lrow[ib] = lrow[ib] * corrb + psb;
            mrow[ia] = ma;
            mrow[ib] = mb;

            ull cp = pack2f(corra, corrb);
#pragma unroll
            for (int c = 0; c < 4; c++) mul2(o2[rp][c], cp);
        }
        __syncthreads();

#pragma unroll 8
        for (int j = 0; j < 64; j++) {
            ulonglong2 p01 = *(const ulonglong2*)&Pst[j * 132 + trow];
            ulonglong2 p23 = *(const ulonglong2*)&Pst[j * 132 + trow + 4];
            float4 vv = *(const float4*)&Vs[j * 68 + tcol];
            ull vd[4] = {dup2(vv.x), dup2(vv.y), dup2(vv.z), dup2(vv.w)};
#pragma unroll
            for (int c = 0; c < 4; c++) {
                fma2(o2[0][c], p01.x, vd[c]);
                fma2(o2[1][c], p01.y, vd[c]);
                fma2(o2[2][c], p23.x, vd[c]);
                fma2(o2[3][c], p23.y, vd[c]);
            }
        }
    }

#pragma unroll
    for (int rp = 0; rp < 4; rp++) {
        float2 c0 = unpk(o2[rp][0]);
        float2 c1 = unpk(o2[rp][1]);
        float2 c2 = unpk(o2[rp][2]);
        float2 c3 = unpk(o2[rp][3]);
        const int ia = 2 * rp, ib = 2 * rp + 1;
        float rla = 1.0f / lrow[ia];
        float rlb = 1.0f / lrow[ib];
        int rowa = b * SEQ + qt * 128 + trow + ia;
        float4 outa = {c0.x * rla, c1.x * rla, c2.x * rla, c3.x * rla};
        float4 outb = {c0.y * rlb, c1.y * rlb, c2.y * rlb, c3.y * rlb};
        *(float4*)(z + (size_t)rowa * D_MODEL + h * DH + tcol)       = outa;
        *(float4*)(z + (size_t)(rowa + 1) * D_MODEL + h * DH + tcol) = outb;
    }
}

// ---------------- launcher ------------------------------------------------------
extern "C" void kernel_launch(void* const* d_in, const int* in_sizes, int n_in,
                              void* d_out, int out_size)
{
    const float* x    = (const float*)d_in[0];
    const float* Wqkv = (const float*)d_in[1];
    const float* Wo   = (const float*)d_in[2];
    const float* sq   = (const float*)d_in[3];
    const float* sk   = (const float*)d_in[4];
    float* out = (float*)d_out;

    float *qkv, *z, *xt, *zt, *ss, *inv;
    cudaGetSymbolAddress((void**)&qkv, g_qkv);
    cudaGetSymbolAddress((void**)&z,   g_z);
    cudaGetSymbolAddress((void**)&xt,  g_xt);
    cudaGetSymbolAddress((void**)&zt,  g_zt);
    cudaGetSymbolAddress((void**)&ss,  g_sumsq);
    cudaGetSymbolAddress((void**)&inv, g_inv);

    static bool attr_done = false;
    if (!attr_done) {
        cudaFuncSetAttribute(flash_kernel, cudaFuncAttributeMaxDynamicSharedMemorySize, 102400);
        attr_done = true;
    }

    zero2_kernel<<<1, 32>>>(ss);

    // x^T
    transpose_kernel<<<dim3(D_MODEL / 32, MROWS / 32), 256>>>(x, xt, MROWS, D_MODEL);

    // QKV GEMM (cp.async, fused q/k sum-of-squares)
    gemm_cpa_kernel<<<dim3(3 * D_MODEL / 128, MROWS / 128), 256>>>(
        xt, Wqkv, qkv, MROWS, 3 * D_MODEL, D_MODEL, ss, 1);

    finalize_kernel<<<1, 32>>>(ss, inv);

    flash_kernel<<<dim3(SEQ / 128, NH, BATCH), 256, 102400>>>(qkv, inv, sq, sk, z);

    // z^T
    transpose_kernel<<<dim3(D_MODEL / 32, MROWS / 32), 256>>>(z, zt, MROWS, D_MODEL);

    // output GEMM
    gemm_cpa_kernel<<<dim3(D_MODEL / 128, MROWS / 128), 256>>>(
        zt, Wo, out, MROWS, D_MODEL, D_MODEL, nullptr, 0);
}

// round 9
// speedup vs baseline: 1.5688x; 1.0469x over previous
#include <cuda_runtime.h>
#include <math.h>
#include <stdint.h>

#define D_MODEL 1024
#define NH 16
#define DH 64
#define BATCH 4
#define SEQ 1024
#define MROWS (BATCH*SEQ)        // 4096
#define QK_COUNT 4194304.0f
#define EPS 1e-6f
#define LOG2E 1.4426950408889634f

typedef unsigned long long ull;

// ---------------- scratch ---------------------------------------------------
__device__ float g_qkv[MROWS * 3 * D_MODEL];   // 48 MB
__device__ float g_z[MROWS * D_MODEL];         // 16 MB
__device__ float g_xt[D_MODEL * MROWS];        // 16 MB  (x^T)
__device__ float g_zt[D_MODEL * MROWS];        // 16 MB  (z^T)
__device__ float g_sumsq[2];
__device__ float g_inv[2];

// ---------------- tiny kernels ----------------------------------------------
__global__ void zero2_kernel(float* p) { if (threadIdx.x < 2) p[threadIdx.x] = 0.0f; }

__global__ void finalize_kernel(const float* __restrict__ ss, float* __restrict__ inv) {
    if (threadIdx.x < 2) {
        float rms = sqrtf(ss[threadIdx.x] / QK_COUNT);
        inv[threadIdx.x] = 1.0f / (rms + EPS);
    }
}

// ---------------- transpose: out[C][R] = in[R][C] -----------------------------
__global__ __launch_bounds__(256)
void transpose_kernel(const float* __restrict__ in, float* __restrict__ out,
                      int R, int C)
{
    __shared__ float tile[32][33];
    const int tx = threadIdx.x & 31;
    const int ty = threadIdx.x >> 5;
    const int bx = blockIdx.x * 32;
    const int by = blockIdx.y * 32;
#pragma unroll
    for (int j = 0; j < 32; j += 8)
        tile[ty + j][tx] = in[(size_t)(by + ty + j) * C + bx + tx];
    __syncthreads();
#pragma unroll
    for (int j = 0; j < 32; j += 8)
        out[(size_t)(bx + ty + j) * R + by + tx] = tile[tx][ty + j];
}

// ---------------- packed f32x2 helpers ----------------------------------------
__device__ __forceinline__ ull dup2(float x) {
    ull r; asm("mov.b64 %0, {%1, %1};" : "=l"(r) : "f"(x)); return r;
}
__device__ __forceinline__ void fma2(ull& d, ull a, ull b) {
    asm("fma.rn.f32x2 %0, %1, %2, %0;" : "+l"(d) : "l"(a), "l"(b));
}
__device__ __forceinline__ float2 unpk(ull v) {
    float2 f; asm("mov.b64 {%0, %1}, %2;" : "=f"(f.x), "=f"(f.y) : "l"(v)); return f;
}
__device__ __forceinline__ float ex2f(float x) {
    float r; asm("ex2.approx.f32 %0, %1;" : "=f"(r) : "f"(x)); return r;
}
__device__ __forceinline__ uint32_t smem_u32(const void* p) {
    uint32_t a;
    asm("{ .reg .u64 t; cvta.to.shared.u64 t, %1; cvt.u32.u64 %0, t; }" : "=r"(a) : "l"(p));
    return a;
}
__device__ __forceinline__ void cpa16(uint32_t dst, const void* src) {
    asm volatile("cp.async.ca.shared.global [%0], [%1], 16;" :: "r"(dst), "l"(src));
}
#define CPA_COMMIT() asm volatile("cp.async.commit_group;" ::: "memory")
#define CPA_WAIT1()  asm volatile("cp.async.wait_group 1;" ::: "memory")

// ---------------- cp.async f32x2 GEMM ------------------------------------------
__global__ __launch_bounds__(256, 2)
void gemm_cpa_kernel(const float* __restrict__ At, const float* __restrict__ B,
                     float* __restrict__ C, int M, int N, int K,
                     float* sumsq, int do_sumsq)
{
    __shared__ __align__(16) float As[3][16][128];
    __shared__ __align__(16) float Bs[3][16][128];
    __shared__ float red[256];

    const int tid  = threadIdx.x;
    const int bcol = blockIdx.x;
    const int brow = blockIdx.y;
    const int trow = (tid >> 4) * 8;
    const int tcol = (tid & 15) * 4;

    const float* Atb = At + brow * 128;
    const float* Bb  = B + bcol * 128;
    const int KT = K / 16;

    const uint32_t sA = smem_u32(As);
    const uint32_t sB = smem_u32(Bs);

    const int c0 = tid, c1 = tid + 256;
    const int kr0 = c0 >> 5, mo0 = (c0 & 31) * 4;
    const int kr1 = c1 >> 5, mo1 = (c1 & 31) * 4;

    auto issue_tile = [&](int kt, int slot) {
        const uint32_t sa = sA + (uint32_t)slot * 8192;
        const uint32_t sb = sB + (uint32_t)slot * 8192;
        cpa16(sa + (uint32_t)(kr0 * 512 + mo0 * 4), Atb + (size_t)(kt * 16 + kr0) * M + mo0);
        cpa16(sa + (uint32_t)(kr1 * 512 + mo1 * 4), Atb + (size_t)(kt * 16 + kr1) * M + mo1);
        cpa16(sb + (uint32_t)(kr0 * 512 + mo0 * 4), Bb  + (size_t)(kt * 16 + kr0) * N + mo0);
        cpa16(sb + (uint32_t)(kr1 * 512 + mo1 * 4), Bb  + (size_t)(kt * 16 + kr1) * N + mo1);
        CPA_COMMIT();
    };

    ull acc[4][8];
#pragma unroll
    for (int rp = 0; rp < 4; rp++)
#pragma unroll
        for (int j = 0; j < 8; j++) acc[rp][j] = 0ULL;

    issue_tile(0, 0);
    issue_tile(1, 1);

    for (int t = 0; t < KT; t++) {
        const int s = t % 3;
        CPA_WAIT1();
        __syncthreads();
        if (t + 2 < KT) issue_tile(t + 2, (t + 2) % 3);
        else            CPA_COMMIT();          // empty group keeps wait count uniform

#pragma unroll
        for (int kk = 0; kk < 16; kk++) {
            ulonglong2 a01 = *(const ulonglong2*)&As[s][kk][trow];
            ulonglong2 a23 = *(const ulonglong2*)&As[s][kk][trow + 4];
            float4 b0 = *(const float4*)&Bs[s][kk][tcol];
            float4 b1 = *(const float4*)&Bs[s][kk][tcol + 64];
            ull bd[8] = {dup2(b0.x), dup2(b0.y), dup2(b0.z), dup2(b0.w),
                         dup2(b1.x), dup2(b1.y), dup2(b1.z), dup2(b1.w)};
#pragma unroll
            for (int j = 0; j < 8; j++) {
                fma2(acc[0][j], a01.x, bd[j]);
                fma2(acc[1][j], a01.y, bd[j]);
                fma2(acc[2][j], a23.x, bd[j]);
                fma2(acc[3][j], a23.y, bd[j]);
            }
        }
    }

    const int colbase = bcol * 128;
    float ss = 0.0f;
#pragma unroll
    for (int rp = 0; rp < 4; rp++) {
        float2 u[8];
#pragma unroll
        for (int j = 0; j < 8; j++) u[j] = unpk(acc[rp][j]);
        const int rowa = brow * 128 + trow + 2 * rp;
        float4 a0 = {u[0].x, u[1].x, u[2].x, u[3].x};
        float4 a1 = {u[4].x, u[5].x, u[6].x, u[7].x};
        float4 b0 = {u[0].y, u[1].y, u[2].y, u[3].y};
        float4 b1 = {u[4].y, u[5].y, u[6].y, u[7].y};
        *(float4*)(C + (size_t)rowa * N + colbase + tcol)            = a0;
        *(float4*)(C + (size_t)rowa * N + colbase + tcol + 64)       = a1;
        *(float4*)(C + (size_t)(rowa + 1) * N + colbase + tcol)      = b0;
        *(float4*)(C + (size_t)(rowa + 1) * N + colbase + tcol + 64) = b1;
        if (do_sumsq && colbase < 2048)
            ss += a0.x*a0.x + a0.y*a0.y + a0.z*a0.z + a0.w*a0.w
                + a1.x*a1.x + a1.y*a1.y + a1.z*a1.z + a1.w*a1.w
                + b0.x*b0.x + b0.y*b0.y + b0.z*b0.z + b0.w*b0.w
                + b1.x*b1.x + b1.y*b1.y + b1.z*b1.z + b1.w*b1.w;
    }

    if (do_sumsq && colbase < 2048) {
        red[tid] = ss;
        __syncthreads();
        for (int s2 = 128; s2 > 0; s2 >>= 1) {
            if (tid < s2) red[tid] += red[tid + s2];
            __syncthreads();
        }
        if (tid == 0) atomicAdd(&sumsq[colbase < 1024 ? 0 : 1], red[0]);
    }
}

// ---------------- Flash attention: no-rescale softmax (exp2, no shfl in loop) --
// Safe because q,k are globally RMS-normalized: s ~ N(0,64), max|s| ~ 50,
// e^50 = 5e21 << fp32 max. log2(e) folded into Q scale -> p = EX2(s') directly.
__global__ __launch_bounds__(256, 2)
void flash_kernel(const float* __restrict__ qkv, const float* __restrict__ inv,
                  const float* __restrict__ scale_q, const float* __restrict__ scale_k,
                  float* __restrict__ z)
{
    extern __shared__ float sm[];
    float* Qst = sm;                    // [d][r]  stride 132 (scaled, incl. LOG2E)
    float* Kst = Qst + 64 * 132;        // [d][c]  stride 68  (raw)
    float* Vs  = Kst + 64 * 68;         // [j][c]  stride 68
    float* Pst = Vs  + 64 * 68;         // [j][r]  stride 132

    const int tid = threadIdx.x;
    const int qt  = blockIdx.x;
    const int h   = blockIdx.y;
    const int b   = blockIdx.z;
    const int trow = (tid >> 4) * 8;
    const int tcol = (tid & 15) * 4;

    const float wsc = inv[0] * inv[1] * LOG2E;

    {
        const int base = b * SEQ + qt * 128;
#pragma unroll
        for (int l = 0; l < 8; l++) {
            int idx = tid + l * 256;
            int r   = idx >> 4;
            int d   = (idx & 15) * 4;
            float4 v = *(const float4*)(qkv + (size_t)(base + r) * 3072 + h * DH + d);
            Qst[(d + 0) * 132 + r] = v.x * wsc * scale_q[d + 0] * scale_k[d + 0];
            Qst[(d + 1) * 132 + r] = v.y * wsc * scale_q[d + 1] * scale_k[d + 1];
            Qst[(d + 2) * 132 + r] = v.z * wsc * scale_q[d + 2] * scale_k[d + 2];
            Qst[(d + 3) * 132 + r] = v.w * wsc * scale_q[d + 3] * scale_k[d + 3];
        }
    }

    ull o2[4][4];
    float lp[8];                         // per-thread partial row sums (own 4 cols)
#pragma unroll
    for (int i = 0; i < 8; i++) lp[i] = 0.0f;
#pragma unroll
    for (int rp = 0; rp < 4; rp++)
#pragma unroll
        for (int c = 0; c < 4; c++) o2[rp][c] = 0ULL;

    for (int t = 0; t < 16; t++) {
        __syncthreads();
#pragma unroll
        for (int u = 0; u < 4; u++) {
            int idx = tid + u * 256;
            int c   = idx >> 4;
            int d   = (idx & 15) * 4;
            int srow = b * SEQ + t * 64 + c;
            float4 kv = *(const float4*)(qkv + (size_t)srow * 3072 + 1024 + h * DH + d);
            Kst[(d + 0) * 68 + c] = kv.x;
            Kst[(d + 1) * 68 + c] = kv.y;
            Kst[(d + 2) * 68 + c] = kv.z;
            Kst[(d + 3) * 68 + c] = kv.w;
            float4 vv = *(const float4*)(qkv + (size_t)srow * 3072 + 2048 + h * DH + d);
            *(float4*)&Vs[c * 68 + d] = vv;
        }
        __syncthreads();

        // ---- S' = (Q*log2e) @ K^T, row-pair packed ----
        ull s2[4][4];
#pragma unroll
        for (int rp = 0; rp < 4; rp++)
#pragma unroll
            for (int c = 0; c < 4; c++) s2[rp][c] = 0ULL;

#pragma unroll 8
        for (int d = 0; d < 64; d++) {
            ulonglong2 q01 = *(const ulonglong2*)&Qst[d * 132 + trow];
            ulonglong2 q23 = *(const ulonglong2*)&Qst[d * 132 + trow + 4];
            float4 kv = *(const float4*)&Kst[d * 68 + tcol];
            ull kd[4] = {dup2(kv.x), dup2(kv.y), dup2(kv.z), dup2(kv.w)};
#pragma unroll
            for (int c = 0; c < 4; c++) {
                fma2(s2[0][c], q01.x, kd[c]);
                fma2(s2[1][c], q01.y, kd[c]);
                fma2(s2[2][c], q23.x, kd[c]);
                fma2(s2[3][c], q23.y, kd[c]);
            }
        }

        // ---- p = 2^{s'}; accumulate partial row sums; store P ----
#pragma unroll
        for (int rp = 0; rp < 4; rp++) {
            float2 c0 = unpk(s2[rp][0]);
            float2 c1 = unpk(s2[rp][1]);
            float2 c2 = unpk(s2[rp][2]);
            float2 c3 = unpk(s2[rp][3]);
            float pa0 = ex2f(c0.x), pb0 = ex2f(c0.y);
            float pa1 = ex2f(c1.x), pb1 = ex2f(c1.y);
            float pa2 = ex2f(c2.x), pb2 = ex2f(c2.y);
            float pa3 = ex2f(c3.x), pb3 = ex2f(c3.y);

            *(float2*)&Pst[(tcol + 0) * 132 + trow + 2 * rp] = make_float2(pa0, pb0);
            *(float2*)&Pst[(tcol + 1) * 132 + trow + 2 * rp] = make_float2(pa1, pb1);
            *(float2*)&Pst[(tcol + 2) * 132 + trow + 2 * rp] = make_float2(pa2, pb2);
            *(float2*)&Pst[(tcol + 3) * 132 + trow + 2 * rp] = make_float2(pa3, pb3);

            lp[2 * rp]     += (pa0 + pa1) + (pa2 + pa3);
            lp[2 * rp + 1] += (pb0 + pb1) + (pb2 + pb3);
        }
        __syncthreads();

        // ---- O += P @ V, row-pair packed ----
#pragma unroll 8
        for (int j = 0; j < 64; j++) {
            ulonglong2 p01 = *(const ulonglong2*)&Pst[j * 132 + trow];
            ulonglong2 p23 = *(const ulonglong2*)&Pst[j * 132 + trow + 4];
            float4 vv = *(const float4*)&Vs[j * 68 + tcol];
            ull vd[4] = {dup2(vv.x), dup2(vv.y), dup2(vv.z), dup2(vv.w)};
#pragma unroll
            for (int c = 0; c < 4; c++) {
                fma2(o2[0][c], p01.x, vd[c]);
                fma2(o2[1][c], p01.y, vd[c]);
                fma2(o2[2][c], p23.x, vd[c]);
                fma2(o2[3][c], p23.y, vd[c]);
            }
        }
    }

    // ---- reduce row sums across the 16 lanes owning each row (once) ----
#pragma unroll
    for (int i = 0; i < 8; i++) {
#pragma unroll
        for (int off = 8; off >= 1; off >>= 1)
            lp[i] += __shfl_xor_sync(0xffffffffu, lp[i], off);
    }

    // ---- epilogue: z = O / l ----
#pragma unroll
    for (int rp = 0; rp < 4; rp++) {
        float2 c0 = unpk(o2[rp][0]);
        float2 c1 = unpk(o2[rp][1]);
        float2 c2 = unpk(o2[rp][2]);
        float2 c3 = unpk(o2[rp][3]);
        const int ia = 2 * rp, ib = 2 * rp + 1;
        float rla = 1.0f / lp[ia];
        float rlb = 1.0f / lp[ib];
        int rowa = b * SEQ + qt * 128 + trow + ia;
        float4 outa = {c0.x * rla, c1.x * rla, c2.x * rla, c3.x * rla};
        float4 outb = {c0.y * rlb, c1.y * rlb, c2.y * rlb, c3.y * rlb};
        *(float4*)(z + (size_t)rowa * D_MODEL + h * DH + tcol)       = outa;
        *(float4*)(z + (size_t)(rowa + 1) * D_MODEL + h * DH + tcol) = outb;
    }
}

// ---------------- launcher ------------------------------------------------------
extern "C" void kernel_launch(void* const* d_in, const int* in_sizes, int n_in,
                              void* d_out, int out_size)
{
    const float* x    = (const float*)d_in[0];
    const float* Wqkv = (const float*)d_in[1];
    const float* Wo   = (const float*)d_in[2];
    const float* sq   = (const float*)d_in[3];
    const float* sk   = (const float*)d_in[4];
    float* out = (float*)d_out;

    float *qkv, *z, *xt, *zt, *ss, *inv;
    cudaGetSymbolAddress((void**)&qkv, g_qkv);
    cudaGetSymbolAddress((void**)&z,   g_z);
    cudaGetSymbolAddress((void**)&xt,  g_xt);
    cudaGetSymbolAddress((void**)&zt,  g_zt);
    cudaGetSymbolAddress((void**)&ss,  g_sumsq);
    cudaGetSymbolAddress((void**)&inv, g_inv);

    static bool attr_done = false;
    if (!attr_done) {
        cudaFuncSetAttribute(flash_kernel, cudaFuncAttributeMaxDynamicSharedMemorySize, 102400);
        attr_done = true;
    }

    zero2_kernel<<<1, 32>>>(ss);

    transpose_kernel<<<dim3(D_MODEL / 32, MROWS / 32), 256>>>(x, xt, MROWS, D_MODEL);

    gemm_cpa_kernel<<<dim3(3 * D_MODEL / 128, MROWS / 128), 256>>>(
        xt, Wqkv, qkv, MROWS, 3 * D_MODEL, D_MODEL, ss, 1);

    finalize_kernel<<<1, 32>>>(ss, inv);

    flash_kernel<<<dim3(SEQ / 128, NH, BATCH), 256, 102400>>>(qkv, inv, sq, sk, z);

    transpose_kernel<<<dim3(D_MODEL / 32, MROWS / 32), 256>>>(z, zt, MROWS, D_MODEL);

    gemm_cpa_kernel<<<dim3(D_MODEL / 128, MROWS / 128), 256>>>(
        zt, Wo, out, MROWS, D_MODEL, D_MODEL, nullptr, 0);
}

// round 10
// speedup vs baseline: 1.5934x; 1.0157x over previous
#include <cuda_runtime.h>
#include <math.h>
#include <stdint.h>

#define D_MODEL 1024
#define NH 16
#define DH 64
#define BATCH 4
#define SEQ 1024
#define MROWS (BATCH*SEQ)        // 4096
#define QK_COUNT 4194304.0f
#define EPS 1e-6f
#define LOG2E 1.4426950408889634f

typedef unsigned long long ull;

// ---------------- scratch ---------------------------------------------------
__device__ float g_qkv[MROWS * 3 * D_MODEL];   // 48 MB
__device__ float g_z[MROWS * D_MODEL];         // 16 MB
__device__ float g_xt[D_MODEL * MROWS];        // 16 MB  (x^T)
__device__ float g_zt[D_MODEL * MROWS];        // 16 MB  (z^T)
__device__ float g_sumsq[2];
__device__ float g_inv[2];

// ---------------- tiny kernels ----------------------------------------------
__global__ void zero2_kernel(float* p) { if (threadIdx.x < 2) p[threadIdx.x] = 0.0f; }

__global__ void finalize_kernel(const float* __restrict__ ss, float* __restrict__ inv) {
    if (threadIdx.x < 2) {
        float rms = sqrtf(ss[threadIdx.x] / QK_COUNT);
        inv[threadIdx.x] = 1.0f / (rms + EPS);
    }
}

// ---------------- transpose: out[C][R] = in[R][C] -----------------------------
__global__ __launch_bounds__(256)
void transpose_kernel(const float* __restrict__ in, float* __restrict__ out,
                      int R, int C)
{
    __shared__ float tile[32][33];
    const int tx = threadIdx.x & 31;
    const int ty = threadIdx.x >> 5;
    const int bx = blockIdx.x * 32;
    const int by = blockIdx.y * 32;
#pragma unroll
    for (int j = 0; j < 32; j += 8)
        tile[ty + j][tx] = in[(size_t)(by + ty + j) * C + bx + tx];
    __syncthreads();
#pragma unroll
    for (int j = 0; j < 32; j += 8)
        out[(size_t)(bx + ty + j) * R + by + tx] = tile[tx][ty + j];
}

// ---------------- packed f32x2 helpers ----------------------------------------
__device__ __forceinline__ ull dup2(float x) {
    ull r; asm("mov.b64 %0, {%1, %1};" : "=l"(r) : "f"(x)); return r;
}
__device__ __forceinline__ void fma2(ull& d, ull a, ull b) {
    asm("fma.rn.f32x2 %0, %1, %2, %0;" : "+l"(d) : "l"(a), "l"(b));
}
__device__ __forceinline__ float2 unpk(ull v) {
    float2 f; asm("mov.b64 {%0, %1}, %2;" : "=f"(f.x), "=f"(f.y) : "l"(v)); return f;
}
__device__ __forceinline__ float ex2f(float x) {
    float r; asm("ex2.approx.f32 %0, %1;" : "=f"(r) : "f"(x)); return r;
}
__device__ __forceinline__ uint32_t smem_u32(const void* p) {
    uint32_t a;
    asm("{ .reg .u64 t; cvta.to.shared.u64 t, %1; cvt.u32.u64 %0, t; }" : "=r"(a) : "l"(p));
    return a;
}
__device__ __forceinline__ void cpa16(uint32_t dst, const void* src) {
    asm volatile("cp.async.ca.shared.global [%0], [%1], 16;" :: "r"(dst), "l"(src));
}
#define CPA_COMMIT() asm volatile("cp.async.commit_group;" ::: "memory")
#define CPA_WAIT1()  asm volatile("cp.async.wait_group 1;" ::: "memory")
#define CPA_WAIT0()  asm volatile("cp.async.wait_group 0;" ::: "memory")

// ---------------- cp.async f32x2 GEMM (unchanged from R9) ----------------------
__global__ __launch_bounds__(256, 2)
void gemm_cpa_kernel(const float* __restrict__ At, const float* __restrict__ B,
                     float* __restrict__ C, int M, int N, int K,
                     float* sumsq, int do_sumsq)
{
    __shared__ __align__(16) float As[3][16][128];
    __shared__ __align__(16) float Bs[3][16][128];
    __shared__ float red[256];

    const int tid  = threadIdx.x;
    const int bcol = blockIdx.x;
    const int brow = blockIdx.y;
    const int trow = (tid >> 4) * 8;
    const int tcol = (tid & 15) * 4;

    const float* Atb = At + brow * 128;
    const float* Bb  = B + bcol * 128;
    const int KT = K / 16;

    const uint32_t sA = smem_u32(As);
    const uint32_t sB = smem_u32(Bs);

    const int c0 = tid, c1 = tid + 256;
    const int kr0 = c0 >> 5, mo0 = (c0 & 31) * 4;
    const int kr1 = c1 >> 5, mo1 = (c1 & 31) * 4;

    auto issue_tile = [&](int kt, int slot) {
        const uint32_t sa = sA + (uint32_t)slot * 8192;
        const uint32_t sb = sB + (uint32_t)slot * 8192;
        cpa16(sa + (uint32_t)(kr0 * 512 + mo0 * 4), Atb + (size_t)(kt * 16 + kr0) * M + mo0);
        cpa16(sa + (uint32_t)(kr1 * 512 + mo1 * 4), Atb + (size_t)(kt * 16 + kr1) * M + mo1);
        cpa16(sb + (uint32_t)(kr0 * 512 + mo0 * 4), Bb  + (size_t)(kt * 16 + kr0) * N + mo0);
        cpa16(sb + (uint32_t)(kr1 * 512 + mo1 * 4), Bb  + (size_t)(kt * 16 + kr1) * N + mo1);
        CPA_COMMIT();
    };

    ull acc[4][8];
#pragma unroll
    for (int rp = 0; rp < 4; rp++)
#pragma unroll
        for (int j = 0; j < 8; j++) acc[rp][j] = 0ULL;

    issue_tile(0, 0);
    issue_tile(1, 1);

    for (int t = 0; t < KT; t++) {
        const int s = t % 3;
        CPA_WAIT1();
        __syncthreads();
        if (t + 2 < KT) issue_tile(t + 2, (t + 2) % 3);
        else            CPA_COMMIT();

#pragma unroll
        for (int kk = 0; kk < 16; kk++) {
            ulonglong2 a01 = *(const ulonglong2*)&As[s][kk][trow];
            ulonglong2 a23 = *(const ulonglong2*)&As[s][kk][trow + 4];
            float4 b0 = *(const float4*)&Bs[s][kk][tcol];
            float4 b1 = *(const float4*)&Bs[s][kk][tcol + 64];
            ull bd[8] = {dup2(b0.x), dup2(b0.y), dup2(b0.z), dup2(b0.w),
                         dup2(b1.x), dup2(b1.y), dup2(b1.z), dup2(b1.w)};
#pragma unroll
            for (int j = 0; j < 8; j++) {
                fma2(acc[0][j], a01.x, bd[j]);
                fma2(acc[1][j], a01.y, bd[j]);
                fma2(acc[2][j], a23.x, bd[j]);
                fma2(acc[3][j], a23.y, bd[j]);
            }
        }
    }

    const int colbase = bcol * 128;
    float ss = 0.0f;
#pragma unroll
    for (int rp = 0; rp < 4; rp++) {
        float2 u[8];
#pragma unroll
        for (int j = 0; j < 8; j++) u[j] = unpk(acc[rp][j]);
        const int rowa = brow * 128 + trow + 2 * rp;
        float4 a0 = {u[0].x, u[1].x, u[2].x, u[3].x};
        float4 a1 = {u[4].x, u[5].x, u[6].x, u[7].x};
        float4 b0 = {u[0].y, u[1].y, u[2].y, u[3].y};
        float4 b1 = {u[4].y, u[5].y, u[6].y, u[7].y};
        *(float4*)(C + (size_t)rowa * N + colbase + tcol)            = a0;
        *(float4*)(C + (size_t)rowa * N + colbase + tcol + 64)       = a1;
        *(float4*)(C + (size_t)(rowa + 1) * N + colbase + tcol)      = b0;
        *(float4*)(C + (size_t)(rowa + 1) * N + colbase + tcol + 64) = b1;
        if (do_sumsq && colbase < 2048)
            ss += a0.x*a0.x + a0.y*a0.y + a0.z*a0.z + a0.w*a0.w
                + a1.x*a1.x + a1.y*a1.y + a1.z*a1.z + a1.w*a1.w
                + b0.x*b0.x + b0.y*b0.y + b0.z*b0.z + b0.w*b0.w
                + b1.x*b1.x + b1.y*b1.y + b1.z*b1.z + b1.w*b1.w;
    }

    if (do_sumsq && colbase < 2048) {
        red[tid] = ss;
        __syncthreads();
        for (int s2 = 128; s2 > 0; s2 >>= 1) {
            if (tid < s2) red[tid] += red[tid + s2];
            __syncthreads();
        }
        if (tid == 0) atomicAdd(&sumsq[colbase < 1024 ? 0 : 1], red[0]);
    }
}

// ---------------- Flash attention: pipelined tile loop -------------------------
// Per tile: S(t) + exp(t) overlap V(t) cp.async arrival; PV(t) overlaps K(t+1)
// LDG+STS (K slot dead after S). Two barriers per tile; no exposed loads.
__global__ __launch_bounds__(256, 2)
void flash_kernel(const float* __restrict__ qkv, const float* __restrict__ inv,
                  const float* __restrict__ scale_q, const float* __restrict__ scale_k,
                  float* __restrict__ z)
{
    extern __shared__ float sm[];
    float* Qst = sm;                    // [d][r]  stride 132 (scaled, incl. LOG2E)
    float* Kst = Qst + 64 * 132;        // [d][c]  stride 68  (raw, transposed)
    float* Vs  = Kst + 64 * 68;         // [c][d]  stride 68  (raw, gmem layout)
    float* Pst = Vs  + 64 * 68;         // [j][r]  stride 132

    const int tid = threadIdx.x;
    const int qt  = blockIdx.x;
    const int h   = blockIdx.y;
    const int b   = blockIdx.z;
    const int trow = (tid >> 4) * 8;
    const int tcol = (tid & 15) * 4;

    const float wsc = inv[0] * inv[1] * LOG2E;
    const uint32_t vb = smem_u32(Vs);

    // ---- Q load (scaled) ----
    {
        const int base = b * SEQ + qt * 128;
#pragma unroll
        for (int l = 0; l < 8; l++) {
            int idx = tid + l * 256;
            int r   = idx >> 4;
            int d   = (idx & 15) * 4;
            float4 v = *(const float4*)(qkv + (size_t)(base + r) * 3072 + h * DH + d);
            Qst[(d + 0) * 132 + r] = v.x * wsc * scale_q[d + 0] * scale_k[d + 0];
            Qst[(d + 1) * 132 + r] = v.y * wsc * scale_q[d + 1] * scale_k[d + 1];
            Qst[(d + 2) * 132 + r] = v.z * wsc * scale_q[d + 2] * scale_k[d + 2];
            Qst[(d + 3) * 132 + r] = v.w * wsc * scale_q[d + 3] * scale_k[d + 3];
        }
    }

    // per-thread K/V chunk coords (u=0..3): c = (tid+u*256)>>4, d = (tid&15)*4
    const int kc = tid >> 4;            // +16 per u
    const int kd = (tid & 15) * 4;
    const int base_kv = b * SEQ;

    // ---- prologue: K(0) LDG->STS; sync; V(0) cp.async ----
#pragma unroll
    for (int u = 0; u < 4; u++) {
        int c = kc + u * 16;
        float4 kv = *(const float4*)(qkv + (size_t)(base_kv + c) * 3072 + 1024 + h * DH + kd);
        Kst[(kd + 0) * 68 + c] = kv.x;
        Kst[(kd + 1) * 68 + c] = kv.y;
        Kst[(kd + 2) * 68 + c] = kv.z;
        Kst[(kd + 3) * 68 + c] = kv.w;
    }
    __syncthreads();                    // Q + K0 visible
#pragma unroll
    for (int u = 0; u < 4; u++) {
        int c = kc + u * 16;
        cpa16(vb + (uint32_t)(c * 68 + kd) * 4,
              qkv + (size_t)(base_kv + c) * 3072 + 2048 + h * DH + kd);
    }
    CPA_COMMIT();

    ull o2[4][4];
    float lp[8];
#pragma unroll
    for (int i = 0; i < 8; i++) lp[i] = 0.0f;
#pragma unroll
    for (int rp = 0; rp < 4; rp++)
#pragma unroll
        for (int c = 0; c < 4; c++) o2[rp][c] = 0ULL;

    for (int t = 0; t < 16; t++) {
        // ---- S' = (Q*log2e) @ K^T, row-pair packed (K(t) in smem) ----
        ull s2[4][4];
#pragma unroll
        for (int rp = 0; rp < 4; rp++)
#pragma unroll
            for (int c = 0; c < 4; c++) s2[rp][c] = 0ULL;

#pragma unroll 8
        for (int d = 0; d < 64; d++) {
            ulonglong2 q01 = *(const ulonglong2*)&Qst[d * 132 + trow];
            ulonglong2 q23 = *(const ulonglong2*)&Qst[d * 132 + trow + 4];
            float4 kv = *(const float4*)&Kst[d * 68 + tcol];
            ull kd4[4] = {dup2(kv.x), dup2(kv.y), dup2(kv.z), dup2(kv.w)};
#pragma unroll
            for (int c = 0; c < 4; c++) {
                fma2(s2[0][c], q01.x, kd4[c]);
                fma2(s2[1][c], q01.y, kd4[c]);
                fma2(s2[2][c], q23.x, kd4[c]);
                fma2(s2[3][c], q23.y, kd4[c]);
            }
        }

        // ---- p = 2^{s'}; partial row sums; store P ----
#pragma unroll
        for (int rp = 0; rp < 4; rp++) {
            float2 c0 = unpk(s2[rp][0]);
            float2 c1 = unpk(s2[rp][1]);
            float2 c2 = unpk(s2[rp][2]);
            float2 c3 = unpk(s2[rp][3]);
            float pa0 = ex2f(c0.x), pb0 = ex2f(c0.y);
            float pa1 = ex2f(c1.x), pb1 = ex2f(c1.y);
            float pa2 = ex2f(c2.x), pb2 = ex2f(c2.y);
            float pa3 = ex2f(c3.x), pb3 = ex2f(c3.y);

            *(float2*)&Pst[(tcol + 0) * 132 + trow + 2 * rp] = make_float2(pa0, pb0);
            *(float2*)&Pst[(tcol + 1) * 132 + trow + 2 * rp] = make_float2(pa1, pb1);
            *(float2*)&Pst[(tcol + 2) * 132 + trow + 2 * rp] = make_float2(pa2, pb2);
            *(float2*)&Pst[(tcol + 3) * 132 + trow + 2 * rp] = make_float2(pa3, pb3);

            lp[2 * rp]     += (pa0 + pa1) + (pa2 + pa3);
            lp[2 * rp + 1] += (pb0 + pb1) + (pb2 + pb3);
        }
        CPA_WAIT0();                    // own V(t) chunks landed
        __syncthreads();                // publish P + V(t); all warps done with K(t)

        // ---- K(t+1) prefetch (LDG now, STS mid-PV) ----
        const bool pref = (t + 1) < 16;
        float4 rk0, rk1, rk2, rk3;
        if (pref) {
            const int srow = base_kv + (t + 1) * 64;
            rk0 = *(const float4*)(qkv + (size_t)(srow + kc)      * 3072 + 1024 + h * DH + kd);
            rk1 = *(const float4*)(qkv + (size_t)(srow + kc + 16) * 3072 + 1024 + h * DH + kd);
            rk2 = *(const float4*)(qkv + (size_t)(srow + kc + 32) * 3072 + 1024 + h * DH + kd);
            rk3 = *(const float4*)(qkv + (size_t)(srow + kc + 48) * 3072 + 1024 + h * DH + kd);
        }

        // ---- O += P @ V, first half ----
#pragma unroll 8
        for (int j = 0; j < 32; j++) {
            ulonglong2 p01 = *(const ulonglong2*)&Pst[j * 132 + trow];
            ulonglong2 p23 = *(const ulonglong2*)&Pst[j * 132 + trow + 4];
            float4 vv = *(const float4*)&Vs[j * 68 + tcol];
            ull vd[4] = {dup2(vv.x), dup2(vv.y), dup2(vv.z), dup2(vv.w)};
#pragma unroll
            for (int c = 0; c < 4; c++) {
                fma2(o2[0][c], p01.x, vd[c]);
                fma2(o2[1][c], p01.y, vd[c]);
                fma2(o2[2][c], p23.x, vd[c]);
                fma2(o2[3][c], p23.y, vd[c]);
            }
        }

        // ---- stage K(t+1) into smem (K slot free; PV doesn't touch it) ----
        if (pref) {
            Kst[(kd + 0) * 68 + kc]      = rk0.x;
            Kst[(kd + 1) * 68 + kc]      = rk0.y;
            Kst[(kd + 2) * 68 + kc]      = rk0.z;
            Kst[(kd + 3) * 68 + kc]      = rk0.w;
            Kst[(kd + 0) * 68 + kc + 16] = rk1.x;
            Kst[(kd + 1) * 68 + kc + 16] = rk1.y;
            Kst[(kd + 2) * 68 + kc + 16] = rk1.z;
            Kst[(kd + 3) * 68 + kc + 16] = rk1.w;
            Kst[(kd + 0) * 68 + kc + 32] = rk2.x;
            Kst[(kd + 1) * 68 + kc + 32] = rk2.y;
            Kst[(kd + 2) * 68 + kc + 32] = rk2.z;
            Kst[(kd + 3) * 68 + kc + 32] = rk2.w;
            Kst[(kd + 0) * 68 + kc + 48] = rk3.x;
            Kst[(kd + 1) * 68 + kc + 48] = rk3.y;
            Kst[(kd + 2) * 68 + kc + 48] = rk3.z;
            Kst[(kd + 3) * 68 + kc + 48] = rk3.w;
        }

        // ---- O += P @ V, second half ----
#pragma unroll 8
        for (int j = 32; j < 64; j++) {
            ulonglong2 p01 = *(const ulonglong2*)&Pst[j * 132 + trow];
            ulonglong2 p23 = *(const ulonglong2*)&Pst[j * 132 + trow + 4];
            float4 vv = *(const float4*)&Vs[j * 68 + tcol];
            ull vd[4] = {dup2(vv.x), dup2(vv.y), dup2(vv.z), dup2(vv.w)};
#pragma unroll
            for (int c = 0; c < 4; c++) {
                fma2(o2[0][c], p01.x, vd[c]);
                fma2(o2[1][c], p01.y, vd[c]);
                fma2(o2[2][c], p23.x, vd[c]);
                fma2(o2[3][c], p23.y, vd[c]);
            }
        }

        __syncthreads();                // PV(t) done (V,P free); K(t+1) visible
        if (pref) {
            const int srow = base_kv + (t + 1) * 64;
#pragma unroll
            for (int u = 0; u < 4; u++) {
                int c = kc + u * 16;
                cpa16(vb + (uint32_t)(c * 68 + kd) * 4,
                      qkv + (size_t)(srow + c) * 3072 + 2048 + h * DH + kd);
            }
            CPA_COMMIT();
        }
    }

    // ---- reduce row sums across the 16 lanes owning each row (once) ----
#pragma unroll
    for (int i = 0; i < 8; i++) {
#pragma unroll
        for (int off = 8; off >= 1; off >>= 1)
            lp[i] += __shfl_xor_sync(0xffffffffu, lp[i], off);
    }

    // ---- epilogue: z = O / l ----
#pragma unroll
    for (int rp = 0; rp < 4; rp++) {
        float2 c0 = unpk(o2[rp][0]);
        float2 c1 = unpk(o2[rp][1]);
        float2 c2 = unpk(o2[rp][2]);
        float2 c3 = unpk(o2[rp][3]);
        const int ia = 2 * rp, ib = 2 * rp + 1;
        float rla = 1.0f / lp[ia];
        float rlb = 1.0f / lp[ib];
        int rowa = b * SEQ + qt * 128 + trow + ia;
        float4 outa = {c0.x * rla, c1.x * rla, c2.x * rla, c3.x * rla};
        float4 outb = {c0.y * rlb, c1.y * rlb, c2.y * rlb, c3.y * rlb};
        *(float4*)(z + (size_t)rowa * D_MODEL + h * DH + tcol)       = outa;
        *(float4*)(z + (size_t)(rowa + 1) * D_MODEL + h * DH + tcol) = outb;
    }
}

// ---------------- launcher ------------------------------------------------------
extern "C" void kernel_launch(void* const* d_in, const int* in_sizes, int n_in,
                              void* d_out, int out_size)
{
    const float* x    = (const float*)d_in[0];
    const float* Wqkv = (const float*)d_in[1];
    const float* Wo   = (const float*)d_in[2];
    const float* sq   = (const float*)d_in[3];
    const float* sk   = (const float*)d_in[4];
    float* out = (float*)d_out;

    float *qkv, *z, *xt, *zt, *ss, *inv;
    cudaGetSymbolAddress((void**)&qkv, g_qkv);
    cudaGetSymbolAddress((void**)&z,   g_z);
    cudaGetSymbolAddress((void**)&xt,  g_xt);
    cudaGetSymbolAddress((void**)&zt,  g_zt);
    cudaGetSymbolAddress((void**)&ss,  g_sumsq);
    cudaGetSymbolAddress((void**)&inv, g_inv);

    static bool attr_done = false;
    if (!attr_done) {
        cudaFuncSetAttribute(flash_kernel, cudaFuncAttributeMaxDynamicSharedMemorySize, 102400);
        attr_done = true;
    }

    zero2_kernel<<<1, 32>>>(ss);

    transpose_kernel<<<dim3(D_MODEL / 32, MROWS / 32), 256>>>(x, xt, MROWS, D_MODEL);

    gemm_cpa_kernel<<<dim3(3 * D_MODEL / 128, MROWS / 128), 256>>>(
        xt, Wqkv, qkv, MROWS, 3 * D_MODEL, D_MODEL, ss, 1);

    finalize_kernel<<<1, 32>>>(ss, inv);

    flash_kernel<<<dim3(SEQ / 128, NH, BATCH), 256, 102400>>>(qkv, inv, sq, sk, z);

    transpose_kernel<<<dim3(D_MODEL / 32, MROWS / 32), 256>>>(z, zt, MROWS, D_MODEL);

    gemm_cpa_kernel<<<dim3(D_MODEL / 128, MROWS / 128), 256>>>(
        zt, Wo, out, MROWS, D_MODEL, D_MODEL, nullptr, 0);
}

// round 11
// speedup vs baseline: 1.6211x; 1.0174x over previous
#include <cuda_runtime.h>
#include <math.h>
#include <stdint.h>

#define D_MODEL 1024
#define NH 16
#define DH 64
#define BATCH 4
#define SEQ 1024
#define MROWS (BATCH*SEQ)        // 4096
#define QK_COUNT 4194304.0f
#define EPS 1e-6f
#define LOG2E 1.4426950408889634f

typedef unsigned long long ull;

// ---------------- scratch ---------------------------------------------------
__device__ float g_qkv[MROWS * 3 * D_MODEL];   // 48 MB
__device__ float g_xt[D_MODEL * MROWS];        // 16 MB  (x^T)
__device__ float g_zt[D_MODEL * MROWS];        // 16 MB  (z^T, written by flash)
__device__ float g_sumsq[2];
__device__ float g_inv[2];

// ---------------- tiny kernels ----------------------------------------------
__global__ void finalize_kernel(const float* __restrict__ ss, float* __restrict__ inv) {
    if (threadIdx.x < 2) {
        float rms = sqrtf(ss[threadIdx.x] / QK_COUNT);
        inv[threadIdx.x] = 1.0f / (rms + EPS);
    }
}

// ---------------- transpose (+ zero sumsq): out[C][R] = in[R][C] ---------------
__global__ __launch_bounds__(256)
void transpose_kernel(const float* __restrict__ in, float* __restrict__ out,
                      int R, int C, float* ss)
{
    __shared__ float tile[32][33];
    if (blockIdx.x == 0 && blockIdx.y == 0 && threadIdx.x < 2) ss[threadIdx.x] = 0.0f;
    const int tx = threadIdx.x & 31;
    const int ty = threadIdx.x >> 5;
    const int bx = blockIdx.x * 32;
    const int by = blockIdx.y * 32;
#pragma unroll
    for (int j = 0; j < 32; j += 8)
        tile[ty + j][tx] = in[(size_t)(by + ty + j) * C + bx + tx];
    __syncthreads();
#pragma unroll
    for (int j = 0; j < 32; j += 8)
        out[(size_t)(bx + ty + j) * R + by + tx] = tile[tx][ty + j];
}

// ---------------- packed f32x2 helpers ----------------------------------------
__device__ __forceinline__ ull dup2(float x) {
    ull r; asm("mov.b64 %0, {%1, %1};" : "=l"(r) : "f"(x)); return r;
}
__device__ __forceinline__ void fma2(ull& d, ull a, ull b) {
    asm("fma.rn.f32x2 %0, %1, %2, %0;" : "+l"(d) : "l"(a), "l"(b));
}
__device__ __forceinline__ float2 unpk(ull v) {
    float2 f; asm("mov.b64 {%0, %1}, %2;" : "=f"(f.x), "=f"(f.y) : "l"(v)); return f;
}
__device__ __forceinline__ float ex2f(float x) {
    float r; asm("ex2.approx.f32 %0, %1;" : "=f"(r) : "f"(x)); return r;
}
__device__ __forceinline__ uint32_t smem_u32(const void* p) {
    uint32_t a;
    asm("{ .reg .u64 t; cvta.to.shared.u64 t, %1; cvt.u32.u64 %0, t; }" : "=r"(a) : "l"(p));
    return a;
}
__device__ __forceinline__ void cpa16(uint32_t dst, const void* src) {
    asm volatile("cp.async.ca.shared.global [%0], [%1], 16;" :: "r"(dst), "l"(src));
}
#define CPA_COMMIT() asm volatile("cp.async.commit_group;" ::: "memory")
#define CPA_WAIT1()  asm volatile("cp.async.wait_group 1;" ::: "memory")
#define CPA_WAIT0()  asm volatile("cp.async.wait_group 0;" ::: "memory")

// ---------------- cp.async f32x2 GEMM (at issue ceiling; unchanged) ------------
__global__ __launch_bounds__(256, 2)
void gemm_cpa_kernel(const float* __restrict__ At, const float* __restrict__ B,
                     float* __restrict__ C, int M, int N, int K,
                     float* sumsq, int do_sumsq)
{
    __shared__ __align__(16) float As[3][16][128];
    __shared__ __align__(16) float Bs[3][16][128];
    __shared__ float red[256];

    const int tid  = threadIdx.x;
    const int bcol = blockIdx.x;
    const int brow = blockIdx.y;
    const int trow = (tid >> 4) * 8;
    const int tcol = (tid & 15) * 4;

    const float* Atb = At + brow * 128;
    const float* Bb  = B + bcol * 128;
    const int KT = K / 16;

    const uint32_t sA = smem_u32(As);
    const uint32_t sB = smem_u32(Bs);

    const int c0 = tid, c1 = tid + 256;
    const int kr0 = c0 >> 5, mo0 = (c0 & 31) * 4;
    const int kr1 = c1 >> 5, mo1 = (c1 & 31) * 4;

    auto issue_tile = [&](int kt, int slot) {
        const uint32_t sa = sA + (uint32_t)slot * 8192;
        const uint32_t sb = sB + (uint32_t)slot * 8192;
        cpa16(sa + (uint32_t)(kr0 * 512 + mo0 * 4), Atb + (size_t)(kt * 16 + kr0) * M + mo0);
        cpa16(sa + (uint32_t)(kr1 * 512 + mo1 * 4), Atb + (size_t)(kt * 16 + kr1) * M + mo1);
        cpa16(sb + (uint32_t)(kr0 * 512 + mo0 * 4), Bb  + (size_t)(kt * 16 + kr0) * N + mo0);
        cpa16(sb + (uint32_t)(kr1 * 512 + mo1 * 4), Bb  + (size_t)(kt * 16 + kr1) * N + mo1);
        CPA_COMMIT();
    };

    ull acc[4][8];
#pragma unroll
    for (int rp = 0; rp < 4; rp++)
#pragma unroll
        for (int j = 0; j < 8; j++) acc[rp][j] = 0ULL;

    issue_tile(0, 0);
    issue_tile(1, 1);

    for (int t = 0; t < KT; t++) {
        const int s = t % 3;
        CPA_WAIT1();
        __syncthreads();
        if (t + 2 < KT) issue_tile(t + 2, (t + 2) % 3);
        else            CPA_COMMIT();

#pragma unroll
        for (int kk = 0; kk < 16; kk++) {
            ulonglong2 a01 = *(const ulonglong2*)&As[s][kk][trow];
            ulonglong2 a23 = *(const ulonglong2*)&As[s][kk][trow + 4];
            float4 b0 = *(const float4*)&Bs[s][kk][tcol];
            float4 b1 = *(const float4*)&Bs[s][kk][tcol + 64];
            ull bd[8] = {dup2(b0.x), dup2(b0.y), dup2(b0.z), dup2(b0.w),
                         dup2(b1.x), dup2(b1.y), dup2(b1.z), dup2(b1.w)};
#pragma unroll
            for (int j = 0; j < 8; j++) {
                fma2(acc[0][j], a01.x, bd[j]);
                fma2(acc[1][j], a01.y, bd[j]);
                fma2(acc[2][j], a23.x, bd[j]);
                fma2(acc[3][j], a23.y, bd[j]);
            }
        }
    }

    const int colbase = bcol * 128;
    float ss = 0.0f;
#pragma unroll
    for (int rp = 0; rp < 4; rp++) {
        float2 u[8];
#pragma unroll
        for (int j = 0; j < 8; j++) u[j] = unpk(acc[rp][j]);
        const int rowa = brow * 128 + trow + 2 * rp;
        float4 a0 = {u[0].x, u[1].x, u[2].x, u[3].x};
        float4 a1 = {u[4].x, u[5].x, u[6].x, u[7].x};
        float4 b0 = {u[0].y, u[1].y, u[2].y, u[3].y};
        float4 b1 = {u[4].y, u[5].y, u[6].y, u[7].y};
        *(float4*)(C + (size_t)rowa * N + colbase + tcol)            = a0;
        *(float4*)(C + (size_t)rowa * N + colbase + tcol + 64)       = a1;
        *(float4*)(C + (size_t)(rowa + 1) * N + colbase + tcol)      = b0;
        *(float4*)(C + (size_t)(rowa + 1) * N + colbase + tcol + 64) = b1;
        if (do_sumsq && colbase < 2048)
            ss += a0.x*a0.x + a0.y*a0.y + a0.z*a0.z + a0.w*a0.w
                + a1.x*a1.x + a1.y*a1.y + a1.z*a1.z + a1.w*a1.w
                + b0.x*b0.x + b0.y*b0.y + b0.z*b0.z + b0.w*b0.w
                + b1.x*b1.x + b1.y*b1.y + b1.z*b1.z + b1.w*b1.w;
    }

    if (do_sumsq && colbase < 2048) {
        red[tid] = ss;
        __syncthreads();
        for (int s2 = 128; s2 > 0; s2 >>= 1) {
            if (tid < s2) red[tid] += red[tid + s2];
            __syncthreads();
        }
        if (tid == 0) atomicAdd(&sumsq[colbase < 1024 ? 0 : 1], red[0]);
    }
}

// ---------------- Flash attention: 64-row q-tiles, 128 threads, 3 CTAs/SM ------
// Same pipelined schedule as R10. Writes z^T directly (32B-contiguous per col).
// smem: Q/K/V/P each 64x68 floats = 69632 B total.
__global__ __launch_bounds__(128, 3)
void flash_kernel(const float* __restrict__ qkv, const float* __restrict__ inv,
                  const float* __restrict__ scale_q, const float* __restrict__ scale_k,
                  float* __restrict__ zt)
{
    extern __shared__ float sm[];
    float* Qst = sm;                    // [d][r] stride 68 (scaled, incl. LOG2E)
    float* Kst = Qst + 64 * 68;         // [d][c] stride 68 (raw)
    float* Vs  = Kst + 64 * 68;         // [c][d] stride 68 (raw, gmem layout)
    float* Pst = Vs  + 64 * 68;         // [j][r] stride 68

    const int tid = threadIdx.x;        // 0..127
    const int qt  = blockIdx.x;         // 0..15
    const int h   = blockIdx.y;
    const int b   = blockIdx.z;
    const int trow = (tid >> 4) * 8;    // 0..56
    const int tcol = (tid & 15) * 4;    // 0..60

    const float wsc = inv[0] * inv[1] * LOG2E;
    const uint32_t vb = smem_u32(Vs);

    // ---- Q load (scaled): 64x64 ----
    {
        const int base = b * SEQ + qt * 64;
#pragma unroll
        for (int l = 0; l < 8; l++) {
            int idx = tid + l * 128;
            int r   = idx >> 4;            // 0..63
            int d   = (idx & 15) * 4;
            float4 v = *(const float4*)(qkv + (size_t)(base + r) * 3072 + h * DH + d);
            Qst[(d + 0) * 68 + r] = v.x * wsc * scale_q[d + 0] * scale_k[d + 0];
            Qst[(d + 1) * 68 + r] = v.y * wsc * scale_q[d + 1] * scale_k[d + 1];
            Qst[(d + 2) * 68 + r] = v.z * wsc * scale_q[d + 2] * scale_k[d + 2];
            Qst[(d + 3) * 68 + r] = v.w * wsc * scale_q[d + 3] * scale_k[d + 3];
        }
    }

    const int kc = tid >> 4;            // +8 per u (u<8) -> c 0..63
    const int kd = (tid & 15) * 4;
    const int base_kv = b * SEQ;

    // ---- prologue: K(0) LDG->STS; sync; V(0) cp.async ----
#pragma unroll
    for (int u = 0; u < 8; u++) {
        int c = kc + u * 8;
        float4 kv = *(const float4*)(qkv + (size_t)(base_kv + c) * 3072 + 1024 + h * DH + kd);
        Kst[(kd + 0) * 68 + c] = kv.x;
        Kst[(kd + 1) * 68 + c] = kv.y;
        Kst[(kd + 2) * 68 + c] = kv.z;
        Kst[(kd + 3) * 68 + c] = kv.w;
    }
    __syncthreads();
#pragma unroll
    for (int u = 0; u < 8; u++) {
        int c = kc + u * 8;
        cpa16(vb + (uint32_t)(c * 68 + kd) * 4,
              qkv + (size_t)(base_kv + c) * 3072 + 2048 + h * DH + kd);
    }
    CPA_COMMIT();

    ull o2[4][4];
    float lp[8];
#pragma unroll
    for (int i = 0; i < 8; i++) lp[i] = 0.0f;
#pragma unroll
    for (int rp = 0; rp < 4; rp++)
#pragma unroll
        for (int c = 0; c < 4; c++) o2[rp][c] = 0ULL;

    for (int t = 0; t < 16; t++) {
        // ---- S' = (Q*log2e) @ K^T ----
        ull s2[4][4];
#pragma unroll
        for (int rp = 0; rp < 4; rp++)
#pragma unroll
            for (int c = 0; c < 4; c++) s2[rp][c] = 0ULL;

#pragma unroll 8
        for (int d = 0; d < 64; d++) {
            ulonglong2 q01 = *(const ulonglong2*)&Qst[d * 68 + trow];
            ulonglong2 q23 = *(const ulonglong2*)&Qst[d * 68 + trow + 4];
            float4 kv = *(const float4*)&Kst[d * 68 + tcol];
            ull kd4[4] = {dup2(kv.x), dup2(kv.y), dup2(kv.z), dup2(kv.w)};
#pragma unroll
            for (int c = 0; c < 4; c++) {
                fma2(s2[0][c], q01.x, kd4[c]);
                fma2(s2[1][c], q01.y, kd4[c]);
                fma2(s2[2][c], q23.x, kd4[c]);
                fma2(s2[3][c], q23.y, kd4[c]);
            }
        }

        // ---- p = 2^{s'}; partial row sums; store P ----
#pragma unroll
        for (int rp = 0; rp < 4; rp++) {
            float2 c0 = unpk(s2[rp][0]);
            float2 c1 = unpk(s2[rp][1]);
            float2 c2 = unpk(s2[rp][2]);
            float2 c3 = unpk(s2[rp][3]);
            float pa0 = ex2f(c0.x), pb0 = ex2f(c0.y);
            float pa1 = ex2f(c1.x), pb1 = ex2f(c1.y);
            float pa2 = ex2f(c2.x), pb2 = ex2f(c2.y);
            float pa3 = ex2f(c3.x), pb3 = ex2f(c3.y);

            *(float2*)&Pst[(tcol + 0) * 68 + trow + 2 * rp] = make_float2(pa0, pb0);
            *(float2*)&Pst[(tcol + 1) * 68 + trow + 2 * rp] = make_float2(pa1, pb1);
            *(float2*)&Pst[(tcol + 2) * 68 + trow + 2 * rp] = make_float2(pa2, pb2);
            *(float2*)&Pst[(tcol + 3) * 68 + trow + 2 * rp] = make_float2(pa3, pb3);

            lp[2 * rp]     += (pa0 + pa1) + (pa2 + pa3);
            lp[2 * rp + 1] += (pb0 + pb1) + (pb2 + pb3);
        }
        CPA_WAIT0();
        __syncthreads();                // P + V(t) visible; K(t) fully consumed

        // ---- K(t+1) prefetch (LDG now, STS mid-PV) ----
        const bool pref = (t + 1) < 16;
        float4 rk[8];
        if (pref) {
            const int srow = base_kv + (t + 1) * 64;
#pragma unroll
            for (int u = 0; u < 8; u++)
                rk[u] = *(const float4*)(qkv + (size_t)(srow + kc + u * 8) * 3072 + 1024 + h * DH + kd);
        }

        // ---- O += P @ V, first half ----
#pragma unroll 8
        for (int j = 0; j < 32; j++) {
            ulonglong2 p01 = *(const ulonglong2*)&Pst[j * 68 + trow];
            ulonglong2 p23 = *(const ulonglong2*)&Pst[j * 68 + trow + 4];
            float4 vv = *(const float4*)&Vs[j * 68 + tcol];
            ull vd[4] = {dup2(vv.x), dup2(vv.y), dup2(vv.z), dup2(vv.w)};
#pragma unroll
            for (int c = 0; c < 4; c++) {
                fma2(o2[0][c], p01.x, vd[c]);
                fma2(o2[1][c], p01.y, vd[c]);
                fma2(o2[2][c], p23.x, vd[c]);
                fma2(o2[3][c], p23.y, vd[c]);
            }
        }

        // ---- stage K(t+1) ----
        if (pref) {
#pragma unroll
            for (int u = 0; u < 8; u++) {
                int c = kc + u * 8;
                Kst[(kd + 0) * 68 + c] = rk[u].x;
                Kst[(kd + 1) * 68 + c] = rk[u].y;
                Kst[(kd + 2) * 68 + c] = rk[u].z;
                Kst[(kd + 3) * 68 + c] = rk[u].w;
            }
        }

        // ---- O += P @ V, second half ----
#pragma unroll 8
        for (int j = 32; j < 64; j++) {
            ulonglong2 p01 = *(const ulonglong2*)&Pst[j * 68 + trow];
            ulonglong2 p23 = *(const ulonglong2*)&Pst[j * 68 + trow + 4];
            float4 vv = *(const float4*)&Vs[j * 68 + tcol];
            ull vd[4] = {dup2(vv.x), dup2(vv.y), dup2(vv.z), dup2(vv.w)};
#pragma unroll
            for (int c = 0; c < 4; c++) {
                fma2(o2[0][c], p01.x, vd[c]);
                fma2(o2[1][c], p01.y, vd[c]);
                fma2(o2[2][c], p23.x, vd[c]);
                fma2(o2[3][c], p23.y, vd[c]);
            }
        }

        __syncthreads();                // PV done; K(t+1) visible
        if (pref) {
            const int srow = base_kv + (t + 1) * 64;
#pragma unroll
            for (int u = 0; u < 8; u++) {
                int c = kc + u * 8;
                cpa16(vb + (uint32_t)(c * 68 + kd) * 4,
                      qkv + (size_t)(srow + c) * 3072 + 2048 + h * DH + kd);
            }
            CPA_COMMIT();
        }
    }

    // ---- reduce row sums across the 16 owning lanes ----
#pragma unroll
    for (int i = 0; i < 8; i++) {
#pragma unroll
        for (int off = 8; off >= 1; off >>= 1)
            lp[i] += __shfl_xor_sync(0xffffffffu, lp[i], off);
    }

    // ---- epilogue: write z^T directly ----
    {
        float rl[8];
#pragma unroll
        for (int i = 0; i < 8; i++) rl[i] = 1.0f / lp[i];
        const int colb = h * DH + tcol;
        const int rowb = b * SEQ + qt * 64 + trow;
        float2 u0, u1, u2, u3;
#pragma unroll
        for (int cc = 0; cc < 4; cc++) {
            u0 = unpk(o2[0][cc]); u1 = unpk(o2[1][cc]);
            u2 = unpk(o2[2][cc]); u3 = unpk(o2[3][cc]);
            float4 w0 = {u0.x * rl[0], u0.y * rl[1], u1.x * rl[2], u1.y * rl[3]};
            float4 w1 = {u2.x * rl[4], u2.y * rl[5], u3.x * rl[6], u3.y * rl[7]};
            *(float4*)(zt + (size_t)(colb + cc) * MROWS + rowb)     = w0;
            *(float4*)(zt + (size_t)(colb + cc) * MROWS + rowb + 4) = w1;
        }
    }
}

// ---------------- launcher ------------------------------------------------------
extern "C" void kernel_launch(void* const* d_in, const int* in_sizes, int n_in,
                              void* d_out, int out_size)
{
    const float* x    = (const float*)d_in[0];
    const float* Wqkv = (const float*)d_in[1];
    const float* Wo   = (const float*)d_in[2];
    const float* sq   = (const float*)d_in[3];
    const float* sk   = (const float*)d_in[4];
    float* out = (float*)d_out;

    float *qkv, *xt, *zt, *ss, *inv;
    cudaGetSymbolAddress((void**)&qkv, g_qkv);
    cudaGetSymbolAddress((void**)&xt,  g_xt);
    cudaGetSymbolAddress((void**)&zt,  g_zt);
    cudaGetSymbolAddress((void**)&ss,  g_sumsq);
    cudaGetSymbolAddress((void**)&inv, g_inv);

    static bool attr_done = false;
    if (!attr_done) {
        cudaFuncSetAttribute(flash_kernel, cudaFuncAttributeMaxDynamicSharedMemorySize, 69632);
        attr_done = true;
    }

    // x^T (+ zero sumsq)
    transpose_kernel<<<dim3(D_MODEL / 32, MROWS / 32), 256>>>(x, xt, MROWS, D_MODEL, ss);

    // QKV GEMM (fused q/k sum-of-squares)
    gemm_cpa_kernel<<<dim3(3 * D_MODEL / 128, MROWS / 128), 256>>>(
        xt, Wqkv, qkv, MROWS, 3 * D_MODEL, D_MODEL, ss, 1);

    finalize_kernel<<<1, 32>>>(ss, inv);

    // flash: 64-row q-tiles, writes z^T
    flash_kernel<<<dim3(SEQ / 64, NH, BATCH), 128, 69632>>>(qkv, inv, sq, sk, zt);

    // output GEMM reads z^T directly
    gemm_cpa_kernel<<<dim3(D_MODEL / 128, MROWS / 128), 256>>>(
        zt, Wo, out, MROWS, D_MODEL, D_MODEL, nullptr, 0);
}